// round 4
// baseline (speedup 1.0000x reference)
#include <cuda_runtime.h>
#include <cmath>

// Problem dims (fixed per reference setup_inputs)
#define BB 32
#define TT 4096
#define LL 32
#define DD 512
#define NN 64
#define ROWS (BB*NN)          // 2048

// ---------------- scratch (device globals; no allocs allowed) ----------------
__device__ float g_logits[BB*TT*NN];        // [B*T][64]   32 MB
__device__ float g_m[ROWS];                 // softmax max per (b,n)
__device__ float g_rs[ROWS];                // 1/sumexp per (b,n)
__device__ float g_featraw[ROWS*DD];        // pre-LN feat
__device__ float g_U[ROWS*2048];            // [feat | A | feat*A | feat*Bmat]  16 MB
__device__ float g_cat[ROWS*DD];            // pre-LN2 output

__device__ __forceinline__ float gelu_exact(float x) {
    return 0.5f * x * (1.0f + erff(x * 0.70710678118654752f));
}

// =====================================================================
// K1: fused  logits = GELU(X@w1 + b1) @ w2 + b2   per 64-token tile
// grid 2048, 256 thr, dyn smem 182528 B
// =====================================================================
#define K1_SMEM ((64*512 + 3*64*64 + 512 + 64) * 4)
__global__ void __launch_bounds__(256) k_logits(
    const float* __restrict__ input, const float* __restrict__ w1,
    const float* __restrict__ b1, const float* __restrict__ w2,
    const float* __restrict__ b2)
{
    extern __shared__ float sm[];
    float* Xs  = sm;            // [64][512]
    float* Ws  = Xs + 64*512;   // [64][64]
    float* Hs  = Ws + 64*64;    // [64][64]
    float* W2s = Hs + 64*64;    // [64][64]
    float* b1s = W2s + 64*64;   // [512]
    float* b2s = b1s + 512;     // [64]

    const int tid = threadIdx.x;
    const size_t t0 = (size_t)blockIdx.x * 64;

    {   // token tile: 8192 float4
        const float4* gx = (const float4*)(input + t0*DD);
        float4* x4 = (float4*)Xs;
        #pragma unroll
        for (int i = 0; i < 32; i++) x4[tid + 256*i] = gx[tid + 256*i];
    }
    for (int i = tid; i < 512; i += 256) b1s[i] = b1[i];
    if (tid < 64) b2s[tid] = b2[tid];

    const int ty = tid >> 4, tx = tid & 15;
    const int r0 = ty * 4, c0 = tx * 4;
    float accL[4][4] = {};

    for (int jc = 0; jc < 8; jc++) {
        __syncthreads();                       // prev GEMM2 done with Hs/W2s
        {   // w2 chunk rows jc*64..+63 (contiguous 4096 floats)
            const float4* gw2 = (const float4*)(w2 + jc*64*NN);
            float4* s4 = (float4*)W2s;
            #pragma unroll
            for (int i = 0; i < 4; i++) s4[tid + 256*i] = gw2[tid + 256*i];
        }
        float acc[4][4] = {};
        for (int kt = 0; kt < 8; kt++) {
            __syncthreads();                   // prev Ws reads done
            {
                float4* s4 = (float4*)Ws;
                #pragma unroll
                for (int i = 0; i < 4; i++) {
                    int idx = tid + 256*i;
                    int rr = idx >> 4, cc = (idx & 15) * 4;
                    s4[idx] = *(const float4*)(w1 + (size_t)(kt*64 + rr)*DD + jc*64 + cc);
                }
            }
            __syncthreads();
            const float* xp = Xs + kt*64;
            #pragma unroll 8
            for (int kk = 0; kk < 64; kk++) {
                float a0 = xp[(r0+0)*DD + kk];
                float a1 = xp[(r0+1)*DD + kk];
                float a2 = xp[(r0+2)*DD + kk];
                float a3 = xp[(r0+3)*DD + kk];
                float4 bv = *(const float4*)(Ws + kk*64 + c0);
                acc[0][0] += a0*bv.x; acc[0][1] += a0*bv.y; acc[0][2] += a0*bv.z; acc[0][3] += a0*bv.w;
                acc[1][0] += a1*bv.x; acc[1][1] += a1*bv.y; acc[1][2] += a1*bv.z; acc[1][3] += a1*bv.w;
                acc[2][0] += a2*bv.x; acc[2][1] += a2*bv.y; acc[2][2] += a2*bv.z; acc[2][3] += a2*bv.w;
                acc[3][0] += a3*bv.x; acc[3][1] += a3*bv.y; acc[3][2] += a3*bv.z; acc[3][3] += a3*bv.w;
            }
        }
        // bias + GELU -> Hs
        #pragma unroll
        for (int i = 0; i < 4; i++) {
            float4 h;
            h.x = gelu_exact(acc[i][0] + b1s[jc*64 + c0+0]);
            h.y = gelu_exact(acc[i][1] + b1s[jc*64 + c0+1]);
            h.z = gelu_exact(acc[i][2] + b1s[jc*64 + c0+2]);
            h.w = gelu_exact(acc[i][3] + b1s[jc*64 + c0+3]);
            *(float4*)(Hs + (r0+i)*64 + c0) = h;
        }
        __syncthreads();
        // accumulate logits: accL += Hs @ W2s
        #pragma unroll 8
        for (int kk = 0; kk < 64; kk++) {
            float a0 = Hs[(r0+0)*64 + kk];
            float a1 = Hs[(r0+1)*64 + kk];
            float a2 = Hs[(r0+2)*64 + kk];
            float a3 = Hs[(r0+3)*64 + kk];
            float4 bv = *(const float4*)(W2s + kk*64 + c0);
            accL[0][0] += a0*bv.x; accL[0][1] += a0*bv.y; accL[0][2] += a0*bv.z; accL[0][3] += a0*bv.w;
            accL[1][0] += a1*bv.x; accL[1][1] += a1*bv.y; accL[1][2] += a1*bv.z; accL[1][3] += a1*bv.w;
            accL[2][0] += a2*bv.x; accL[2][1] += a2*bv.y; accL[2][2] += a2*bv.z; accL[2][3] += a2*bv.w;
            accL[3][0] += a3*bv.x; accL[3][1] += a3*bv.y; accL[3][2] += a3*bv.z; accL[3][3] += a3*bv.w;
        }
    }
    float* outp = g_logits + t0*NN;
    #pragma unroll
    for (int i = 0; i < 4; i++) {
        float4 o;
        o.x = accL[i][0] + b2s[c0+0];
        o.y = accL[i][1] + b2s[c0+1];
        o.z = accL[i][2] + b2s[c0+2];
        o.w = accL[i][3] + b2s[c0+3];
        *(float4*)(outp + (r0+i)*NN + c0) = o;
    }
}

// =====================================================================
// K2: per-(b,n) online max & sumexp over T   (grid 32, 256 thr)
// =====================================================================
__global__ void __launch_bounds__(256) k_stats()
{
    const int b = blockIdx.x, tid = threadIdx.x;
    const int n = tid & 63, tg = tid >> 6;
    const float* base = g_logits + (size_t)b*TT*NN;
    float m = -1e30f, s = 0.0f;
    for (int t = tg; t < TT; t += 4) {
        float v = base[(size_t)t*NN + n];
        if (v <= m) s += __expf(v - m);
        else { s = s * __expf(m - v) + 1.0f; m = v; }
    }
    __shared__ float sm_m[4][64], sm_s[4][64];
    sm_m[tg][n] = m; sm_s[tg][n] = s;
    __syncthreads();
    if (tid < 64) {
        float M = sm_m[0][tid];
        #pragma unroll
        for (int i = 1; i < 4; i++) M = fmaxf(M, sm_m[i][tid]);
        float S = 0.0f;
        #pragma unroll
        for (int i = 0; i < 4; i++) S += sm_s[i][tid] * __expf(sm_m[i][tid] - M);
        g_m[b*NN + tid] = M;
        g_rs[b*NN + tid] = 1.0f / S;
    }
}

// =====================================================================
// K3: feat_raw[b,n,d] = (1/S) * sum_t exp(logit - m) * input[b,t,d]
// grid (4, 32): 64x128 output tile, K=4096.  256 thr, static smem.
// =====================================================================
__global__ void __launch_bounds__(256) k_feat(const float* __restrict__ input)
{
    __shared__ float Ps[32*64];     // exp'd logits tile [t][n]
    __shared__ float Xs[32*128];    // input tile [t][d]
    __shared__ float ms[64], rss[64];

    const int b = blockIdx.y;
    const int d0 = blockIdx.x * 128;
    const int tid = threadIdx.x;
    if (tid < 64) { ms[tid] = g_m[b*NN + tid]; rss[tid] = g_rs[b*NN + tid]; }

    const int ty = tid >> 4, tx = tid & 15;
    const int n0 = ty * 4, c0 = tx * 8;
    float acc[4][8] = {};

    const float* L = g_logits + (size_t)b*TT*NN;
    const float* X = input + (size_t)b*TT*DD;

    for (int kt = 0; kt < 128; kt++) {
        const int t0 = kt * 32;
        __syncthreads();
        #pragma unroll
        for (int i = 0; i < 8; i++) {
            int idx = tid + 256*i;
            int t = idx >> 6, n = idx & 63;
            Ps[t*64 + n] = __expf(L[(size_t)(t0+t)*NN + n] - ms[n]);
        }
        #pragma unroll
        for (int i = 0; i < 4; i++) {
            int idx = tid + 256*i;
            int t = idx >> 5, c4 = idx & 31;
            ((float4*)Xs)[idx] = *(const float4*)(X + (size_t)(t0+t)*DD + d0 + c4*4);
        }
        __syncthreads();
        #pragma unroll 8
        for (int kk = 0; kk < 32; kk++) {
            float a0 = Ps[kk*64 + n0+0];
            float a1 = Ps[kk*64 + n0+1];
            float a2 = Ps[kk*64 + n0+2];
            float a3 = Ps[kk*64 + n0+3];
            float4 b0 = *(const float4*)(Xs + kk*128 + c0);
            float4 b1v = *(const float4*)(Xs + kk*128 + c0 + 4);
            acc[0][0]+=a0*b0.x; acc[0][1]+=a0*b0.y; acc[0][2]+=a0*b0.z; acc[0][3]+=a0*b0.w;
            acc[0][4]+=a0*b1v.x; acc[0][5]+=a0*b1v.y; acc[0][6]+=a0*b1v.z; acc[0][7]+=a0*b1v.w;
            acc[1][0]+=a1*b0.x; acc[1][1]+=a1*b0.y; acc[1][2]+=a1*b0.z; acc[1][3]+=a1*b0.w;
            acc[1][4]+=a1*b1v.x; acc[1][5]+=a1*b1v.y; acc[1][6]+=a1*b1v.z; acc[1][7]+=a1*b1v.w;
            acc[2][0]+=a2*b0.x; acc[2][1]+=a2*b0.y; acc[2][2]+=a2*b0.z; acc[2][3]+=a2*b0.w;
            acc[2][4]+=a2*b1v.x; acc[2][5]+=a2*b1v.y; acc[2][6]+=a2*b1v.z; acc[2][7]+=a2*b1v.w;
            acc[3][0]+=a3*b0.x; acc[3][1]+=a3*b0.y; acc[3][2]+=a3*b0.z; acc[3][3]+=a3*b0.w;
            acc[3][4]+=a3*b1v.x; acc[3][5]+=a3*b1v.y; acc[3][6]+=a3*b1v.z; acc[3][7]+=a3*b1v.w;
        }
    }
    #pragma unroll
    for (int i = 0; i < 4; i++) {
        float r = rss[n0+i];
        float* dst = g_featraw + (size_t)(b*NN + n0+i)*DD + d0 + c0;
        float4 o0, o1;
        o0.x = acc[i][0]*r; o0.y = acc[i][1]*r; o0.z = acc[i][2]*r; o0.w = acc[i][3]*r;
        o1.x = acc[i][4]*r; o1.y = acc[i][5]*r; o1.z = acc[i][6]*r; o1.w = acc[i][7]*r;
        *(float4*)dst = o0;
        *(float4*)(dst + 4) = o1;
    }
}

// =====================================================================
// LayerNorm helper: one warp per 512-wide row
// =====================================================================
__device__ __forceinline__ void ln_row(const float* __restrict__ src,
                                       float* __restrict__ dst,
                                       const float* __restrict__ gamma,
                                       const float* __restrict__ beta,
                                       int lane)
{
    float4 v[4];
    float s = 0.0f, sq = 0.0f;
    #pragma unroll
    for (int i = 0; i < 4; i++) {
        v[i] = *(const float4*)(src + i*128 + lane*4);
        s  += v[i].x + v[i].y + v[i].z + v[i].w;
        sq += v[i].x*v[i].x + v[i].y*v[i].y + v[i].z*v[i].z + v[i].w*v[i].w;
    }
    #pragma unroll
    for (int o = 16; o > 0; o >>= 1) {
        s  += __shfl_xor_sync(0xffffffffu, s, o);
        sq += __shfl_xor_sync(0xffffffffu, sq, o);
    }
    float mean = s * (1.0f/512.0f);
    float var  = sq * (1.0f/512.0f) - mean*mean;
    float inv  = rsqrtf(var + 1e-5f);
    #pragma unroll
    for (int i = 0; i < 4; i++) {
        int c = i*128 + lane*4;
        float4 g4 = *(const float4*)(gamma + c);
        float4 b4 = *(const float4*)(beta + c);
        float4 o;
        o.x = (v[i].x - mean)*inv*g4.x + b4.x;
        o.y = (v[i].y - mean)*inv*g4.y + b4.y;
        o.z = (v[i].z - mean)*inv*g4.z + b4.z;
        o.w = (v[i].w - mean)*inv*g4.w + b4.w;
        *(float4*)(dst + c) = o;
    }
}

// K4: LN1(feat_raw) -> g_U segment 0.  grid 256, 256 thr
__global__ void __launch_bounds__(256) k_ln1(const float* __restrict__ g,
                                             const float* __restrict__ be)
{
    int warp = threadIdx.x >> 5, lane = threadIdx.x & 31;
    int row = blockIdx.x * 8 + warp;
    ln_row(g_featraw + (size_t)row*DD, g_U + (size_t)row*2048, g, be, lane);
}

// =====================================================================
// K5: per-batch CQA core. grid 32, 256 thr, dyn smem 214016 B
// =====================================================================
#define QS_STRIDE 516
#define K5_SMEM ((LL*QS_STRIDE + NN*DD + 2*NN*33) * 4)
__global__ void __launch_bounds__(256) k_cqa(const float* __restrict__ query)
{
    extern __shared__ float sm[];
    float* qs = sm;                         // [32][516]  (later reused for M)
    float* fs = qs + LL*QS_STRIDE;          // [64][512]
    float* s0 = fs + NN*DD;                 // [64][33]  sim -> sim_c
    float* sr = s0 + NN*33;                 // [64][33]  sim_r

    const int b = blockIdx.x, tid = threadIdx.x;

    for (int i = tid; i < LL*128; i += 256) {
        int l = i >> 7, c4 = i & 127;
        *(float4*)(qs + l*QS_STRIDE + c4*4) =
            *(const float4*)(query + (size_t)(b*LL + l)*DD + c4*4);
    }
    for (int i = tid; i < NN*128; i += 256) {
        int n = i >> 7, c4 = i & 127;
        *(float4*)(fs + n*DD + c4*4) =
            *(const float4*)(g_U + (size_t)(b*NN + n)*2048 + c4*4);
    }
    __syncthreads();

    // sim[n][l] = feat[n]·query[l]
    {
        const int l = tid & 31, ng = tid >> 5;
        #pragma unroll
        for (int j = 0; j < 8; j++) {
            int n = ng + 8*j;
            float s = 0.0f;
            #pragma unroll 4
            for (int k = 0; k < DD; k++) s += fs[n*DD + k] * qs[l*QS_STRIDE + k];
            s0[n*33 + l] = s;
        }
    }
    __syncthreads();
    // row softmax (over l=32) -> sr
    if (tid < 64) {
        int n = tid;
        float M = -1e30f;
        for (int l = 0; l < 32; l++) M = fmaxf(M, s0[n*33 + l]);
        float S = 0.0f;
        for (int l = 0; l < 32; l++) S += __expf(s0[n*33 + l] - M);
        float inv = 1.0f / S;
        for (int l = 0; l < 32; l++) sr[n*33 + l] = __expf(s0[n*33 + l] - M) * inv;
    }
    __syncthreads();
    // col softmax (over n=64) in place -> s0 becomes sim_c
    if (tid < 32) {
        int l = tid;
        float M = -1e30f;
        for (int n = 0; n < 64; n++) M = fmaxf(M, s0[n*33 + l]);
        float S = 0.0f;
        for (int n = 0; n < 64; n++) S += __expf(s0[n*33 + l] - M);
        float inv = 1.0f / S;
        for (int n = 0; n < 64; n++) s0[n*33 + l] = __expf(s0[n*33 + l] - M) * inv;
    }
    __syncthreads();

    // A = sim_r @ query ; write A and feat*A into U
    for (int i = tid; i < NN*128; i += 256) {
        int n = i >> 7, c4 = i & 127, d = c4*4;
        float4 a = {0,0,0,0};
        #pragma unroll
        for (int l = 0; l < 32; l++) {
            float w = sr[n*33 + l];
            float4 qv = *(const float4*)(qs + l*QS_STRIDE + d);
            a.x += w*qv.x; a.y += w*qv.y; a.z += w*qv.z; a.w += w*qv.w;
        }
        float4 f = *(const float4*)(fs + n*DD + d);
        float* dst = g_U + (size_t)(b*NN + n)*2048;
        *(float4*)(dst + 512 + d) = a;
        float4 e3 = {f.x*a.x, f.y*a.y, f.z*a.z, f.w*a.w};
        *(float4*)(dst + 1024 + d) = e3;
    }
    __syncthreads();   // qs consumption done -> reuse for M

    // M[l] = sum_n sim_c[n][l] * feat[n]
    for (int i = tid; i < LL*128; i += 256) {
        int l = i >> 7, c4 = i & 127, d = c4*4;
        float4 m = {0,0,0,0};
        #pragma unroll 8
        for (int n = 0; n < 64; n++) {
            float w = s0[n*33 + l];
            float4 fv = *(const float4*)(fs + n*DD + d);
            m.x += w*fv.x; m.y += w*fv.y; m.z += w*fv.z; m.w += w*fv.w;
        }
        *(float4*)(qs + l*QS_STRIDE + d) = m;
    }
    __syncthreads();

    // Bmat = sim_r @ M ; write feat*Bmat into U
    for (int i = tid; i < NN*128; i += 256) {
        int n = i >> 7, c4 = i & 127, d = c4*4;
        float4 bm = {0,0,0,0};
        #pragma unroll
        for (int l = 0; l < 32; l++) {
            float w = sr[n*33 + l];
            float4 mv = *(const float4*)(qs + l*QS_STRIDE + d);
            bm.x += w*mv.x; bm.y += w*mv.y; bm.z += w*mv.z; bm.w += w*mv.w;
        }
        float4 f = *(const float4*)(fs + n*DD + d);
        float4 e4 = {f.x*bm.x, f.y*bm.y, f.z*bm.z, f.w*bm.w};
        *(float4*)(g_U + (size_t)(b*NN + n)*2048 + 1536 + d) = e4;
    }
}

// =====================================================================
// K6: cat = U[2048,2048] @ [wf1;wf2;wf3;wf4] + (bf1+bf2+bf3+bf4)
// grid (8, 32): 64x64 tiles. 256 thr, static smem 32.25 KB
// =====================================================================
__global__ void __launch_bounds__(256) k_headgemm(
    const float* __restrict__ wf1, const float* __restrict__ wf2,
    const float* __restrict__ wf3, const float* __restrict__ wf4,
    const float* __restrict__ bf1, const float* __restrict__ bf2,
    const float* __restrict__ bf3, const float* __restrict__ bf4)
{
    __shared__ float Us[64*64];
    __shared__ float Ws[64*64];
    __shared__ float bsum[64];

    const int n0 = blockIdx.x * 64;
    const int m0 = blockIdx.y * 64;
    const int tid = threadIdx.x;
    if (tid < 64) bsum[tid] = bf1[n0+tid] + bf2[n0+tid] + bf3[n0+tid] + bf4[n0+tid];

    const int ty = tid >> 4, tx = tid & 15;
    const int r0 = ty * 4, c0 = tx * 4;
    float acc[4][4] = {};

    for (int kt = 0; kt < 32; kt++) {
        __syncthreads();
        const float* wseg = (kt < 8) ? wf1 : (kt < 16) ? wf2 : (kt < 24) ? wf3 : wf4;
        const int rbase = (kt & 7) * 64;
        #pragma unroll
        for (int i = 0; i < 4; i++) {
            int idx = tid + 256*i;
            int r = idx >> 4, c4 = (idx & 15) * 4;
            ((float4*)Us)[idx] = *(const float4*)(g_U + (size_t)(m0+r)*2048 + kt*64 + c4);
            ((float4*)Ws)[idx] = *(const float4*)(wseg + (size_t)(rbase+r)*DD + n0 + c4);
        }
        __syncthreads();
        #pragma unroll 8
        for (int kk = 0; kk < 64; kk++) {
            float a0 = Us[(r0+0)*64 + kk];
            float a1 = Us[(r0+1)*64 + kk];
            float a2 = Us[(r0+2)*64 + kk];
            float a3 = Us[(r0+3)*64 + kk];
            float4 bv = *(const float4*)(Ws + kk*64 + c0);
            acc[0][0]+=a0*bv.x; acc[0][1]+=a0*bv.y; acc[0][2]+=a0*bv.z; acc[0][3]+=a0*bv.w;
            acc[1][0]+=a1*bv.x; acc[1][1]+=a1*bv.y; acc[1][2]+=a1*bv.z; acc[1][3]+=a1*bv.w;
            acc[2][0]+=a2*bv.x; acc[2][1]+=a2*bv.y; acc[2][2]+=a2*bv.z; acc[2][3]+=a2*bv.w;
            acc[3][0]+=a3*bv.x; acc[3][1]+=a3*bv.y; acc[3][2]+=a3*bv.z; acc[3][3]+=a3*bv.w;
        }
    }
    #pragma unroll
    for (int i = 0; i < 4; i++) {
        float4 o;
        o.x = acc[i][0] + bsum[c0+0];
        o.y = acc[i][1] + bsum[c0+1];
        o.z = acc[i][2] + bsum[c0+2];
        o.w = acc[i][3] + bsum[c0+3];
        *(float4*)(g_cat + (size_t)(m0+r0+i)*DD + n0 + c0) = o;
    }
}

// K7: LN2(cat) -> d_out.  grid 256, 256 thr
__global__ void __launch_bounds__(256) k_ln2(const float* __restrict__ g,
                                             const float* __restrict__ be,
                                             float* __restrict__ out)
{
    int warp = threadIdx.x >> 5, lane = threadIdx.x & 31;
    int row = blockIdx.x * 8 + warp;
    ln_row(g_cat + (size_t)row*DD, out + (size_t)row*DD, g, be, lane);
}

// =====================================================================
extern "C" void kernel_launch(void* const* d_in, const int* in_sizes, int n_in,
                              void* d_out, int out_size)
{
    const float* input = (const float*)d_in[0];
    const float* query = (const float*)d_in[1];
    const float* w1    = (const float*)d_in[2];
    const float* b1    = (const float*)d_in[3];
    const float* w2    = (const float*)d_in[4];
    const float* b2    = (const float*)d_in[5];
    const float* ln1g  = (const float*)d_in[6];
    const float* ln1b  = (const float*)d_in[7];
    const float* wf1   = (const float*)d_in[8];
    const float* bf1   = (const float*)d_in[9];
    const float* wf2   = (const float*)d_in[10];
    const float* bf2   = (const float*)d_in[11];
    const float* wf3   = (const float*)d_in[12];
    const float* bf3   = (const float*)d_in[13];
    const float* wf4   = (const float*)d_in[14];
    const float* bf4   = (const float*)d_in[15];
    const float* ln2g  = (const float*)d_in[16];
    const float* ln2b  = (const float*)d_in[17];
    float* out = (float*)d_out;

    cudaFuncSetAttribute(k_logits, cudaFuncAttributeMaxDynamicSharedMemorySize, K1_SMEM);
    cudaFuncSetAttribute(k_cqa,    cudaFuncAttributeMaxDynamicSharedMemorySize, K5_SMEM);

    k_logits<<<BB*TT/64, 256, K1_SMEM>>>(input, w1, b1, w2, b2);
    k_stats<<<BB, 256>>>();
    k_feat<<<dim3(4, BB), 256>>>(input);
    k_ln1<<<ROWS/8, 256>>>(ln1g, ln1b);
    k_cqa<<<BB, 256, K5_SMEM>>>(query);
    k_headgemm<<<dim3(8, 32), 256>>>(wf1, wf2, wf3, wf4, bf1, bf2, bf3, bf4);
    k_ln2<<<ROWS/8, 256>>>(ln2g, ln2b, out);
}

// round 5
// speedup vs baseline: 1.0006x; 1.0006x over previous
#include <cuda_runtime.h>
#include <cmath>

// Problem dims (fixed per reference setup_inputs)
#define BB 32
#define TT 4096
#define LL 32
#define DD 512
#define NN 64
#define ROWS (BB*NN)          // 2048

// ---------------- scratch (device globals; no allocs allowed) ----------------
__device__ float g_logits[BB*TT*NN];        // [B*T][64]   32 MB
__device__ float g_m[ROWS];                 // softmax max per (b,n)
__device__ float g_rs[ROWS];                // 1/sumexp per (b,n)
__device__ float g_featraw[ROWS*DD];        // pre-LN feat
__device__ float g_U[ROWS*2048];            // [feat | A | feat*A | feat*Bmat]  16 MB
__device__ float g_cat[ROWS*DD];            // pre-LN2 output

__device__ __forceinline__ float gelu_exact(float x) {
    return 0.5f * x * (1.0f + erff(x * 0.70710678118654752f));
}

// =====================================================================
// K1: fused  logits = GELU(X@w1 + b1) @ w2 + b2   per 64-token tile
// grid 2048, 256 thr, dyn smem 182528 B
// =====================================================================
#define K1_SMEM ((64*512 + 3*64*64 + 512 + 64) * 4)
__global__ void __launch_bounds__(256) k_logits(
    const float* __restrict__ input, const float* __restrict__ w1,
    const float* __restrict__ b1, const float* __restrict__ w2,
    const float* __restrict__ b2)
{
    extern __shared__ float sm[];
    float* Xs  = sm;            // [64][512]
    float* Ws  = Xs + 64*512;   // [64][64]
    float* Hs  = Ws + 64*64;    // [64][64]
    float* W2s = Hs + 64*64;    // [64][64]
    float* b1s = W2s + 64*64;   // [512]
    float* b2s = b1s + 512;     // [64]

    const int tid = threadIdx.x;
    const size_t t0 = (size_t)blockIdx.x * 64;

    {   // token tile: 8192 float4
        const float4* gx = (const float4*)(input + t0*DD);
        float4* x4 = (float4*)Xs;
        #pragma unroll
        for (int i = 0; i < 32; i++) x4[tid + 256*i] = gx[tid + 256*i];
    }
    for (int i = tid; i < 512; i += 256) b1s[i] = b1[i];
    if (tid < 64) b2s[tid] = b2[tid];

    const int ty = tid >> 4, tx = tid & 15;
    const int r0 = ty * 4, c0 = tx * 4;
    float accL[4][4] = {};

    for (int jc = 0; jc < 8; jc++) {
        __syncthreads();                       // prev GEMM2 done with Hs/W2s
        {   // w2 chunk rows jc*64..+63 (contiguous 4096 floats)
            const float4* gw2 = (const float4*)(w2 + jc*64*NN);
            float4* s4 = (float4*)W2s;
            #pragma unroll
            for (int i = 0; i < 4; i++) s4[tid + 256*i] = gw2[tid + 256*i];
        }
        float acc[4][4] = {};
        for (int kt = 0; kt < 8; kt++) {
            __syncthreads();                   // prev Ws reads done
            {
                float4* s4 = (float4*)Ws;
                #pragma unroll
                for (int i = 0; i < 4; i++) {
                    int idx = tid + 256*i;
                    int rr = idx >> 4, cc = (idx & 15) * 4;
                    s4[idx] = *(const float4*)(w1 + (size_t)(kt*64 + rr)*DD + jc*64 + cc);
                }
            }
            __syncthreads();
            const float* xp = Xs + kt*64;
            #pragma unroll 8
            for (int kk = 0; kk < 64; kk++) {
                float a0 = xp[(r0+0)*DD + kk];
                float a1 = xp[(r0+1)*DD + kk];
                float a2 = xp[(r0+2)*DD + kk];
                float a3 = xp[(r0+3)*DD + kk];
                float4 bv = *(const float4*)(Ws + kk*64 + c0);
                acc[0][0] += a0*bv.x; acc[0][1] += a0*bv.y; acc[0][2] += a0*bv.z; acc[0][3] += a0*bv.w;
                acc[1][0] += a1*bv.x; acc[1][1] += a1*bv.y; acc[1][2] += a1*bv.z; acc[1][3] += a1*bv.w;
                acc[2][0] += a2*bv.x; acc[2][1] += a2*bv.y; acc[2][2] += a2*bv.z; acc[2][3] += a2*bv.w;
                acc[3][0] += a3*bv.x; acc[3][1] += a3*bv.y; acc[3][2] += a3*bv.z; acc[3][3] += a3*bv.w;
            }
        }
        // bias + GELU -> Hs
        #pragma unroll
        for (int i = 0; i < 4; i++) {
            float4 h;
            h.x = gelu_exact(acc[i][0] + b1s[jc*64 + c0+0]);
            h.y = gelu_exact(acc[i][1] + b1s[jc*64 + c0+1]);
            h.z = gelu_exact(acc[i][2] + b1s[jc*64 + c0+2]);
            h.w = gelu_exact(acc[i][3] + b1s[jc*64 + c0+3]);
            *(float4*)(Hs + (r0+i)*64 + c0) = h;
        }
        __syncthreads();
        // accumulate logits: accL += Hs @ W2s
        #pragma unroll 8
        for (int kk = 0; kk < 64; kk++) {
            float a0 = Hs[(r0+0)*64 + kk];
            float a1 = Hs[(r0+1)*64 + kk];
            float a2 = Hs[(r0+2)*64 + kk];
            float a3 = Hs[(r0+3)*64 + kk];
            float4 bv = *(const float4*)(W2s + kk*64 + c0);
            accL[0][0] += a0*bv.x; accL[0][1] += a0*bv.y; accL[0][2] += a0*bv.z; accL[0][3] += a0*bv.w;
            accL[1][0] += a1*bv.x; accL[1][1] += a1*bv.y; accL[1][2] += a1*bv.z; accL[1][3] += a1*bv.w;
            accL[2][0] += a2*bv.x; accL[2][1] += a2*bv.y; accL[2][2] += a2*bv.z; accL[2][3] += a2*bv.w;
            accL[3][0] += a3*bv.x; accL[3][1] += a3*bv.y; accL[3][2] += a3*bv.z; accL[3][3] += a3*bv.w;
        }
    }
    float* outp = g_logits + t0*NN;
    #pragma unroll
    for (int i = 0; i < 4; i++) {
        float4 o;
        o.x = accL[i][0] + b2s[c0+0];
        o.y = accL[i][1] + b2s[c0+1];
        o.z = accL[i][2] + b2s[c0+2];
        o.w = accL[i][3] + b2s[c0+3];
        *(float4*)(outp + (r0+i)*NN + c0) = o;
    }
}

// =====================================================================
// K2: per-(b,n) online max & sumexp over T   (grid 32, 256 thr)
// =====================================================================
__global__ void __launch_bounds__(256) k_stats()
{
    const int b = blockIdx.x, tid = threadIdx.x;
    const int n = tid & 63, tg = tid >> 6;
    const float* base = g_logits + (size_t)b*TT*NN;
    float m = -1e30f, s = 0.0f;
    for (int t = tg; t < TT; t += 4) {
        float v = base[(size_t)t*NN + n];
        if (v <= m) s += __expf(v - m);
        else { s = s * __expf(m - v) + 1.0f; m = v; }
    }
    __shared__ float sm_m[4][64], sm_s[4][64];
    sm_m[tg][n] = m; sm_s[tg][n] = s;
    __syncthreads();
    if (tid < 64) {
        float M = sm_m[0][tid];
        #pragma unroll
        for (int i = 1; i < 4; i++) M = fmaxf(M, sm_m[i][tid]);
        float S = 0.0f;
        #pragma unroll
        for (int i = 0; i < 4; i++) S += sm_s[i][tid] * __expf(sm_m[i][tid] - M);
        g_m[b*NN + tid] = M;
        g_rs[b*NN + tid] = 1.0f / S;
    }
}

// =====================================================================
// K3: feat_raw[b,n,d] = (1/S) * sum_t exp(logit - m) * input[b,t,d]
// grid (4, 32): 64x128 output tile, K=4096.  256 thr, static smem.
// =====================================================================
__global__ void __launch_bounds__(256) k_feat(const float* __restrict__ input)
{
    __shared__ float Ps[32*64];     // exp'd logits tile [t][n]
    __shared__ float Xs[32*128];    // input tile [t][d]
    __shared__ float ms[64], rss[64];

    const int b = blockIdx.y;
    const int d0 = blockIdx.x * 128;
    const int tid = threadIdx.x;
    if (tid < 64) { ms[tid] = g_m[b*NN + tid]; rss[tid] = g_rs[b*NN + tid]; }

    const int ty = tid >> 4, tx = tid & 15;
    const int n0 = ty * 4, c0 = tx * 8;
    float acc[4][8] = {};

    const float* L = g_logits + (size_t)b*TT*NN;
    const float* X = input + (size_t)b*TT*DD;

    for (int kt = 0; kt < 128; kt++) {
        const int t0 = kt * 32;
        __syncthreads();
        #pragma unroll
        for (int i = 0; i < 8; i++) {
            int idx = tid + 256*i;
            int t = idx >> 6, n = idx & 63;
            Ps[t*64 + n] = __expf(L[(size_t)(t0+t)*NN + n] - ms[n]);
        }
        #pragma unroll
        for (int i = 0; i < 4; i++) {
            int idx = tid + 256*i;
            int t = idx >> 5, c4 = idx & 31;
            ((float4*)Xs)[idx] = *(const float4*)(X + (size_t)(t0+t)*DD + d0 + c4*4);
        }
        __syncthreads();
        #pragma unroll 8
        for (int kk = 0; kk < 32; kk++) {
            float a0 = Ps[kk*64 + n0+0];
            float a1 = Ps[kk*64 + n0+1];
            float a2 = Ps[kk*64 + n0+2];
            float a3 = Ps[kk*64 + n0+3];
            float4 b0 = *(const float4*)(Xs + kk*128 + c0);
            float4 b1v = *(const float4*)(Xs + kk*128 + c0 + 4);
            acc[0][0]+=a0*b0.x; acc[0][1]+=a0*b0.y; acc[0][2]+=a0*b0.z; acc[0][3]+=a0*b0.w;
            acc[0][4]+=a0*b1v.x; acc[0][5]+=a0*b1v.y; acc[0][6]+=a0*b1v.z; acc[0][7]+=a0*b1v.w;
            acc[1][0]+=a1*b0.x; acc[1][1]+=a1*b0.y; acc[1][2]+=a1*b0.z; acc[1][3]+=a1*b0.w;
            acc[1][4]+=a1*b1v.x; acc[1][5]+=a1*b1v.y; acc[1][6]+=a1*b1v.z; acc[1][7]+=a1*b1v.w;
            acc[2][0]+=a2*b0.x; acc[2][1]+=a2*b0.y; acc[2][2]+=a2*b0.z; acc[2][3]+=a2*b0.w;
            acc[2][4]+=a2*b1v.x; acc[2][5]+=a2*b1v.y; acc[2][6]+=a2*b1v.z; acc[2][7]+=a2*b1v.w;
            acc[3][0]+=a3*b0.x; acc[3][1]+=a3*b0.y; acc[3][2]+=a3*b0.z; acc[3][3]+=a3*b0.w;
            acc[3][4]+=a3*b1v.x; acc[3][5]+=a3*b1v.y; acc[3][6]+=a3*b1v.z; acc[3][7]+=a3*b1v.w;
        }
    }
    #pragma unroll
    for (int i = 0; i < 4; i++) {
        float r = rss[n0+i];
        float* dst = g_featraw + (size_t)(b*NN + n0+i)*DD + d0 + c0;
        float4 o0, o1;
        o0.x = acc[i][0]*r; o0.y = acc[i][1]*r; o0.z = acc[i][2]*r; o0.w = acc[i][3]*r;
        o1.x = acc[i][4]*r; o1.y = acc[i][5]*r; o1.z = acc[i][6]*r; o1.w = acc[i][7]*r;
        *(float4*)dst = o0;
        *(float4*)(dst + 4) = o1;
    }
}

// =====================================================================
// LayerNorm helper: one warp per 512-wide row
// =====================================================================
__device__ __forceinline__ void ln_row(const float* __restrict__ src,
                                       float* __restrict__ dst,
                                       const float* __restrict__ gamma,
                                       const float* __restrict__ beta,
                                       int lane)
{
    float4 v[4];
    float s = 0.0f, sq = 0.0f;
    #pragma unroll
    for (int i = 0; i < 4; i++) {
        v[i] = *(const float4*)(src + i*128 + lane*4);
        s  += v[i].x + v[i].y + v[i].z + v[i].w;
        sq += v[i].x*v[i].x + v[i].y*v[i].y + v[i].z*v[i].z + v[i].w*v[i].w;
    }
    #pragma unroll
    for (int o = 16; o > 0; o >>= 1) {
        s  += __shfl_xor_sync(0xffffffffu, s, o);
        sq += __shfl_xor_sync(0xffffffffu, sq, o);
    }
    float mean = s * (1.0f/512.0f);
    float var  = sq * (1.0f/512.0f) - mean*mean;
    float inv  = rsqrtf(var + 1e-5f);
    #pragma unroll
    for (int i = 0; i < 4; i++) {
        int c = i*128 + lane*4;
        float4 g4 = *(const float4*)(gamma + c);
        float4 b4 = *(const float4*)(beta + c);
        float4 o;
        o.x = (v[i].x - mean)*inv*g4.x + b4.x;
        o.y = (v[i].y - mean)*inv*g4.y + b4.y;
        o.z = (v[i].z - mean)*inv*g4.z + b4.z;
        o.w = (v[i].w - mean)*inv*g4.w + b4.w;
        *(float4*)(dst + c) = o;
    }
}

// K4: LN1(feat_raw) -> g_U segment 0.  grid 256, 256 thr
__global__ void __launch_bounds__(256) k_ln1(const float* __restrict__ g,
                                             const float* __restrict__ be)
{
    int warp = threadIdx.x >> 5, lane = threadIdx.x & 31;
    int row = blockIdx.x * 8 + warp;
    ln_row(g_featraw + (size_t)row*DD, g_U + (size_t)row*2048, g, be, lane);
}

// =====================================================================
// K5: per-batch CQA core. grid 32, 256 thr, dyn smem 214016 B
// =====================================================================
#define QS_STRIDE 516
#define K5_SMEM ((LL*QS_STRIDE + NN*DD + 2*NN*33) * 4)
__global__ void __launch_bounds__(256) k_cqa(const float* __restrict__ query)
{
    extern __shared__ float sm[];
    float* qs = sm;                         // [32][516]  (later reused for M)
    float* fs = qs + LL*QS_STRIDE;          // [64][512]
    float* s0 = fs + NN*DD;                 // [64][33]  sim -> sim_c
    float* sr = s0 + NN*33;                 // [64][33]  sim_r

    const int b = blockIdx.x, tid = threadIdx.x;

    for (int i = tid; i < LL*128; i += 256) {
        int l = i >> 7, c4 = i & 127;
        *(float4*)(qs + l*QS_STRIDE + c4*4) =
            *(const float4*)(query + (size_t)(b*LL + l)*DD + c4*4);
    }
    for (int i = tid; i < NN*128; i += 256) {
        int n = i >> 7, c4 = i & 127;
        *(float4*)(fs + n*DD + c4*4) =
            *(const float4*)(g_U + (size_t)(b*NN + n)*2048 + c4*4);
    }
    __syncthreads();

    // sim[n][l] = feat[n]·query[l]
    {
        const int l = tid & 31, ng = tid >> 5;
        #pragma unroll
        for (int j = 0; j < 8; j++) {
            int n = ng + 8*j;
            float s = 0.0f;
            #pragma unroll 4
            for (int k = 0; k < DD; k++) s += fs[n*DD + k] * qs[l*QS_STRIDE + k];
            s0[n*33 + l] = s;
        }
    }
    __syncthreads();
    // row softmax (over l=32) -> sr
    if (tid < 64) {
        int n = tid;
        float M = -1e30f;
        for (int l = 0; l < 32; l++) M = fmaxf(M, s0[n*33 + l]);
        float S = 0.0f;
        for (int l = 0; l < 32; l++) S += __expf(s0[n*33 + l] - M);
        float inv = 1.0f / S;
        for (int l = 0; l < 32; l++) sr[n*33 + l] = __expf(s0[n*33 + l] - M) * inv;
    }
    __syncthreads();
    // col softmax (over n=64) in place -> s0 becomes sim_c
    if (tid < 32) {
        int l = tid;
        float M = -1e30f;
        for (int n = 0; n < 64; n++) M = fmaxf(M, s0[n*33 + l]);
        float S = 0.0f;
        for (int n = 0; n < 64; n++) S += __expf(s0[n*33 + l] - M);
        float inv = 1.0f / S;
        for (int n = 0; n < 64; n++) s0[n*33 + l] = __expf(s0[n*33 + l] - M) * inv;
    }
    __syncthreads();

    // A = sim_r @ query ; write A and feat*A into U
    for (int i = tid; i < NN*128; i += 256) {
        int n = i >> 7, c4 = i & 127, d = c4*4;
        float4 a = {0,0,0,0};
        #pragma unroll
        for (int l = 0; l < 32; l++) {
            float w = sr[n*33 + l];
            float4 qv = *(const float4*)(qs + l*QS_STRIDE + d);
            a.x += w*qv.x; a.y += w*qv.y; a.z += w*qv.z; a.w += w*qv.w;
        }
        float4 f = *(const float4*)(fs + n*DD + d);
        float* dst = g_U + (size_t)(b*NN + n)*2048;
        *(float4*)(dst + 512 + d) = a;
        float4 e3 = {f.x*a.x, f.y*a.y, f.z*a.z, f.w*a.w};
        *(float4*)(dst + 1024 + d) = e3;
    }
    __syncthreads();   // qs consumption done -> reuse for M

    // M[l] = sum_n sim_c[n][l] * feat[n]
    for (int i = tid; i < LL*128; i += 256) {
        int l = i >> 7, c4 = i & 127, d = c4*4;
        float4 m = {0,0,0,0};
        #pragma unroll 8
        for (int n = 0; n < 64; n++) {
            float w = s0[n*33 + l];
            float4 fv = *(const float4*)(fs + n*DD + d);
            m.x += w*fv.x; m.y += w*fv.y; m.z += w*fv.z; m.w += w*fv.w;
        }
        *(float4*)(qs + l*QS_STRIDE + d) = m;
    }
    __syncthreads();

    // Bmat = sim_r @ M ; write feat*Bmat into U
    for (int i = tid; i < NN*128; i += 256) {
        int n = i >> 7, c4 = i & 127, d = c4*4;
        float4 bm = {0,0,0,0};
        #pragma unroll
        for (int l = 0; l < 32; l++) {
            float w = sr[n*33 + l];
            float4 mv = *(const float4*)(qs + l*QS_STRIDE + d);
            bm.x += w*mv.x; bm.y += w*mv.y; bm.z += w*mv.z; bm.w += w*mv.w;
        }
        float4 f = *(const float4*)(fs + n*DD + d);
        float4 e4 = {f.x*bm.x, f.y*bm.y, f.z*bm.z, f.w*bm.w};
        *(float4*)(g_U + (size_t)(b*NN + n)*2048 + 1536 + d) = e4;
    }
}

// =====================================================================
// K6: cat = U[2048,2048] @ [wf1;wf2;wf3;wf4] + (bf1+bf2+bf3+bf4)
// grid (8, 32): 64x64 tiles. 256 thr, static smem 32.25 KB
// =====================================================================
__global__ void __launch_bounds__(256) k_headgemm(
    const float* __restrict__ wf1, const float* __restrict__ wf2,
    const float* __restrict__ wf3, const float* __restrict__ wf4,
    const float* __restrict__ bf1, const float* __restrict__ bf2,
    const float* __restrict__ bf3, const float* __restrict__ bf4)
{
    __shared__ float Us[64*64];
    __shared__ float Ws[64*64];
    __shared__ float bsum[64];

    const int n0 = blockIdx.x * 64;
    const int m0 = blockIdx.y * 64;
    const int tid = threadIdx.x;
    if (tid < 64) bsum[tid] = bf1[n0+tid] + bf2[n0+tid] + bf3[n0+tid] + bf4[n0+tid];

    const int ty = tid >> 4, tx = tid & 15;
    const int r0 = ty * 4, c0 = tx * 4;
    float acc[4][4] = {};

    for (int kt = 0; kt < 32; kt++) {
        __syncthreads();
        const float* wseg = (kt < 8) ? wf1 : (kt < 16) ? wf2 : (kt < 24) ? wf3 : wf4;
        const int rbase = (kt & 7) * 64;
        #pragma unroll
        for (int i = 0; i < 4; i++) {
            int idx = tid + 256*i;
            int r = idx >> 4, c4 = (idx & 15) * 4;
            ((float4*)Us)[idx] = *(const float4*)(g_U + (size_t)(m0+r)*2048 + kt*64 + c4);
            ((float4*)Ws)[idx] = *(const float4*)(wseg + (size_t)(rbase+r)*DD + n0 + c4);
        }
        __syncthreads();
        #pragma unroll 8
        for (int kk = 0; kk < 64; kk++) {
            float a0 = Us[(r0+0)*64 + kk];
            float a1 = Us[(r0+1)*64 + kk];
            float a2 = Us[(r0+2)*64 + kk];
            float a3 = Us[(r0+3)*64 + kk];
            float4 bv = *(const float4*)(Ws + kk*64 + c0);
            acc[0][0]+=a0*bv.x; acc[0][1]+=a0*bv.y; acc[0][2]+=a0*bv.z; acc[0][3]+=a0*bv.w;
            acc[1][0]+=a1*bv.x; acc[1][1]+=a1*bv.y; acc[1][2]+=a1*bv.z; acc[1][3]+=a1*bv.w;
            acc[2][0]+=a2*bv.x; acc[2][1]+=a2*bv.y; acc[2][2]+=a2*bv.z; acc[2][3]+=a2*bv.w;
            acc[3][0]+=a3*bv.x; acc[3][1]+=a3*bv.y; acc[3][2]+=a3*bv.z; acc[3][3]+=a3*bv.w;
        }
    }
    #pragma unroll
    for (int i = 0; i < 4; i++) {
        float4 o;
        o.x = acc[i][0] + bsum[c0+0];
        o.y = acc[i][1] + bsum[c0+1];
        o.z = acc[i][2] + bsum[c0+2];
        o.w = acc[i][3] + bsum[c0+3];
        *(float4*)(g_cat + (size_t)(m0+r0+i)*DD + n0 + c0) = o;
    }
}

// K7: LN2(cat) -> d_out.  grid 256, 256 thr
__global__ void __launch_bounds__(256) k_ln2(const float* __restrict__ g,
                                             const float* __restrict__ be,
                                             float* __restrict__ out)
{
    int warp = threadIdx.x >> 5, lane = threadIdx.x & 31;
    int row = blockIdx.x * 8 + warp;
    ln_row(g_cat + (size_t)row*DD, out + (size_t)row*DD, g, be, lane);
}

// =====================================================================
extern "C" void kernel_launch(void* const* d_in, const int* in_sizes, int n_in,
                              void* d_out, int out_size)
{
    const float* input = (const float*)d_in[0];
    const float* query = (const float*)d_in[1];
    const float* w1    = (const float*)d_in[2];
    const float* b1    = (const float*)d_in[3];
    const float* w2    = (const float*)d_in[4];
    const float* b2    = (const float*)d_in[5];
    const float* ln1g  = (const float*)d_in[6];
    const float* ln1b  = (const float*)d_in[7];
    const float* wf1   = (const float*)d_in[8];
    const float* bf1   = (const float*)d_in[9];
    const float* wf2   = (const float*)d_in[10];
    const float* bf2   = (const float*)d_in[11];
    const float* wf3   = (const float*)d_in[12];
    const float* bf3   = (const float*)d_in[13];
    const float* wf4   = (const float*)d_in[14];
    const float* bf4   = (const float*)d_in[15];
    const float* ln2g  = (const float*)d_in[16];
    const float* ln2b  = (const float*)d_in[17];
    float* out = (float*)d_out;

    cudaFuncSetAttribute(k_logits, cudaFuncAttributeMaxDynamicSharedMemorySize, K1_SMEM);
    cudaFuncSetAttribute(k_cqa,    cudaFuncAttributeMaxDynamicSharedMemorySize, K5_SMEM);

    k_logits<<<BB*TT/64, 256, K1_SMEM>>>(input, w1, b1, w2, b2);
    k_stats<<<BB, 256>>>();
    k_feat<<<dim3(4, BB), 256>>>(input);
    k_ln1<<<ROWS/8, 256>>>(ln1g, ln1b);
    k_cqa<<<BB, 256, K5_SMEM>>>(query);
    k_headgemm<<<dim3(8, 32), 256>>>(wf1, wf2, wf3, wf4, bf1, bf2, bf3, bf4);
    k_ln2<<<ROWS/8, 256>>>(ln2g, ln2b, out);
}

// round 7
// speedup vs baseline: 1.8811x; 1.8800x over previous
#include <cuda_runtime.h>
#include <cuda_bf16.h>
#include <cstdint>
#include <cmath>

// Problem dims (fixed per reference setup_inputs)
#define BB 32
#define TT 4096
#define LL 32
#define DD 512
#define NN 64
#define ROWS (BB*NN)          // 2048

// ---------------- scratch (device globals; no allocs allowed) ----------------
__device__ float g_logits[BB*TT*NN];        // [B*T][64]   32 MB
__device__ float g_m[ROWS];
__device__ float g_rs[ROWS];
__device__ float g_featraw[ROWS*DD];
__device__ float g_U[ROWS*2048];
__device__ float g_cat[ROWS*DD];
// split-bf16 transposed weights (K-major rows)
__device__ __nv_bfloat16 g_w1t_hi[DD*DD];   // [n=512][k=512]
__device__ __nv_bfloat16 g_w1t_lo[DD*DD];
__device__ __nv_bfloat16 g_w2t_hi[NN*DD];   // [n=64][k=512]
__device__ __nv_bfloat16 g_w2t_lo[NN*DD];

__device__ __forceinline__ float gelu_exact(float x) {
    return 0.5f * x * (1.0f + erff(x * 0.70710678118654752f));
}

// ===================== mma.sync / ldmatrix helpers (sm_80+ PTX) ==============
__device__ __forceinline__ uint32_t smem_u32(const void* p) {
    uint32_t a;
    asm("{ .reg .u64 t; cvta.to.shared.u64 t, %1; cvt.u32.u64 %0, t; }" : "=r"(a) : "l"(p));
    return a;
}
__device__ __forceinline__ void ldsm_x4(uint32_t r[4], uint32_t addr) {
    asm volatile("ldmatrix.sync.aligned.m8n8.x4.shared.b16 {%0,%1,%2,%3}, [%4];"
        : "=r"(r[0]), "=r"(r[1]), "=r"(r[2]), "=r"(r[3]) : "r"(addr));
}
__device__ __forceinline__ void ldsm_x2(uint32_t r[2], uint32_t addr) {
    asm volatile("ldmatrix.sync.aligned.m8n8.x2.shared.b16 {%0,%1}, [%2];"
        : "=r"(r[0]), "=r"(r[1]) : "r"(addr));
}
__device__ __forceinline__ void mma_bf16(float* d, const uint32_t* a, const uint32_t* b) {
    asm volatile("mma.sync.aligned.m16n8k16.row.col.f32.bf16.bf16.f32 "
        "{%0,%1,%2,%3}, {%4,%5,%6,%7}, {%8,%9}, {%0,%1,%2,%3};"
        : "+f"(d[0]), "+f"(d[1]), "+f"(d[2]), "+f"(d[3])
        : "r"(a[0]), "r"(a[1]), "r"(a[2]), "r"(a[3]), "r"(b[0]), "r"(b[1]));
}
__device__ __forceinline__ uint32_t pack_bf16(__nv_bfloat16 a, __nv_bfloat16 b) {
    return ((uint32_t)__bfloat16_as_ushort(b) << 16) | (uint32_t)__bfloat16_as_ushort(a);
}
__device__ __forceinline__ void split_bf16(float x, __nv_bfloat16& h, __nv_bfloat16& l) {
    h = __float2bfloat16(x);
    l = __float2bfloat16(x - __bfloat162float(h));
}

// =====================================================================
// K0: prep — transpose + split w1, w2 to bf16 hi/lo (K-major rows)
// =====================================================================
__global__ void __launch_bounds__(256) k_prep(const float* __restrict__ w1,
                                              const float* __restrict__ w2)
{
    int n = blockIdx.x;
    if (n < 512) {
        for (int k = threadIdx.x; k < 512; k += 256) {
            float x = w1[(size_t)k*512 + n];
            __nv_bfloat16 h, l; split_bf16(x, h, l);
            g_w1t_hi[n*512 + k] = h;
            g_w1t_lo[n*512 + k] = l;
        }
    } else {
        int n2 = n - 512;
        for (int k = threadIdx.x; k < 512; k += 256) {
            float x = w2[(size_t)k*64 + n2];
            __nv_bfloat16 h, l; split_bf16(x, h, l);
            g_w2t_hi[n2*512 + k] = h;
            g_w2t_lo[n2*512 + k] = l;
        }
    }
}

// =====================================================================
// K1: split-bf16 mma.sync  logits = GELU(X@w1+b1)@w2 + b2
// grid 1024 (128 tokens/CTA), 512 thr, dyn smem 198912 B
// =====================================================================
// SMEM byte offsets. Row strides padded for conflict-free ldmatrix:
//  X:[128][40 bf16] (80 B/row), W1:[256][40], H:[128][264] (528 B/row), W2:[64][72] (144 B/row)
#define SM_XHI   0
#define SM_XLO   10240
#define SM_W1HI  20480
#define SM_W1LO  40960
#define SM_W2HI  0            // reuses X/W1 region during GEMM2
#define SM_W2LO  9216
#define SM_HHI   61440
#define SM_HLO   129024
#define SM_B1    196608
#define SM_B2    198656
#define K1TC_SMEM 198912

__global__ void __launch_bounds__(512, 1) k_logits_tc(
    const float* __restrict__ input,
    const float* __restrict__ b1, const float* __restrict__ b2)
{
    extern __shared__ char smem[];
    const uint32_t sb = smem_u32(smem);
    const int tid = threadIdx.x;
    const int wid = tid >> 5, lane = tid & 31;
    const int wm = wid & 3, wn = wid >> 2;       // warp grid 4(M) x 4(N)
    const size_t t0 = (size_t)blockIdx.x * 128;

    float* b1s = (float*)(smem + SM_B1);
    float* b2s = (float*)(smem + SM_B2);
    b1s[tid & 511] = b1[tid & 511];
    if (tid < 64) b2s[tid] = b2[tid];

    // per-lane ldmatrix base offsets
    const uint32_t aoffX = (uint32_t)((lane & 15) * 80  + (lane >> 4) * 16);
    const uint32_t boffW = (uint32_t)((lane & 7)  * 80  + ((lane >> 3) & 1) * 16);
    const uint32_t aoffH = (uint32_t)((lane & 15) * 528 + (lane >> 4) * 16);
    const uint32_t boff2 = (uint32_t)((lane & 7)  * 144 + ((lane >> 3) & 1) * 16);
    const int qrow = lane >> 2, qcol = (lane & 3) * 2;

    float acc2[2][2][4];     // GEMM2 accumulators, persist across nc
    #pragma unroll
    for (int i = 0; i < 2; i++)
        #pragma unroll
        for (int j = 0; j < 2; j++)
            #pragma unroll
            for (int k = 0; k < 4; k++) acc2[i][j][k] = 0.0f;

    for (int nc = 0; nc < 2; nc++) {
        float acc[2][8][4];
        #pragma unroll
        for (int i = 0; i < 2; i++)
            #pragma unroll
            for (int j = 0; j < 8; j++)
                #pragma unroll
                for (int k = 0; k < 4; k++) acc[i][j][k] = 0.0f;

        // ---------------- GEMM1: K=512 in 16 chunks of 32 ----------------
        for (int kc = 0; kc < 16; kc++) {
            __syncthreads();    // prior ldmatrix reads of region1 done
            {   // X chunk [128 tok][32 k] fp32 -> bf16 hi/lo
                int row = tid >> 2, seg = tid & 3;
                const float* src = input + (t0 + row)*DD + kc*32 + seg*8;
                float4 v0 = *(const float4*)src;
                float4 v1 = *(const float4*)(src + 4);
                __nv_bfloat16 h[8], l[8];
                split_bf16(v0.x, h[0], l[0]); split_bf16(v0.y, h[1], l[1]);
                split_bf16(v0.z, h[2], l[2]); split_bf16(v0.w, h[3], l[3]);
                split_bf16(v1.x, h[4], l[4]); split_bf16(v1.y, h[5], l[5]);
                split_bf16(v1.z, h[6], l[6]); split_bf16(v1.w, h[7], l[7]);
                uint4 hp = { pack_bf16(h[0],h[1]), pack_bf16(h[2],h[3]),
                             pack_bf16(h[4],h[5]), pack_bf16(h[6],h[7]) };
                uint4 lp = { pack_bf16(l[0],l[1]), pack_bf16(l[2],l[3]),
                             pack_bf16(l[4],l[5]), pack_bf16(l[6],l[7]) };
                *(uint4*)(smem + SM_XHI + row*80 + seg*16) = hp;
                *(uint4*)(smem + SM_XLO + row*80 + seg*16) = lp;
            }
            {   // W1 chunk [256 n][32 k] hi/lo (bf16 copy)
                int n = tid >> 1, part = tid & 1;
                const uint4* sh = (const uint4*)(g_w1t_hi + (size_t)(nc*256 + n)*512 + kc*32 + part*16);
                const uint4* sl = (const uint4*)(g_w1t_lo + (size_t)(nc*256 + n)*512 + kc*32 + part*16);
                uint4 h0 = sh[0], h1 = sh[1];
                uint4 l0 = sl[0], l1 = sl[1];
                char* dh = smem + SM_W1HI + n*80 + part*32;
                char* dl = smem + SM_W1LO + n*80 + part*32;
                *(uint4*)dh = h0; *(uint4*)(dh + 16) = h1;
                *(uint4*)dl = l0; *(uint4*)(dl + 16) = l1;
            }
            __syncthreads();
            const uint32_t xsrc[3] = {SM_XHI, SM_XHI, SM_XLO};
            const uint32_t wsrc[3] = {SM_W1HI, SM_W1LO, SM_W1HI};
            #pragma unroll
            for (int p = 0; p < 3; p++) {
                uint32_t xb = sb + xsrc[p] + aoffX + (uint32_t)(wm*32*80);
                uint32_t wb = sb + wsrc[p] + boffW + (uint32_t)(wn*64*80);
                #pragma unroll
                for (int ks = 0; ks < 2; ks++) {
                    uint32_t a0[4], a1[4];
                    ldsm_x4(a0, xb + ks*32);
                    ldsm_x4(a1, xb + 16*80 + ks*32);
                    #pragma unroll
                    for (int nt = 0; nt < 8; nt++) {
                        uint32_t bf[2];
                        ldsm_x2(bf, wb + nt*8*80 + ks*32);
                        mma_bf16(acc[0][nt], a0, bf);
                        mma_bf16(acc[1][nt], a1, bf);
                    }
                }
            }
        }

        // ------------- epilogue: bias + GELU + split -> H (SMEM) -------------
        __syncthreads();
        #pragma unroll
        for (int mt = 0; mt < 2; mt++)
            #pragma unroll
            for (int nt = 0; nt < 8; nt++)
                #pragma unroll
                for (int h = 0; h < 2; h++) {
                    int row = wm*32 + mt*16 + h*8 + qrow;
                    int col = wn*64 + nt*8 + qcol;
                    float x0 = acc[mt][nt][h*2+0] + b1s[nc*256 + col];
                    float x1 = acc[mt][nt][h*2+1] + b1s[nc*256 + col + 1];
                    float g0 = gelu_exact(x0), g1 = gelu_exact(x1);
                    __nv_bfloat16 hh0, ll0, hh1, ll1;
                    split_bf16(g0, hh0, ll0); split_bf16(g1, hh1, ll1);
                    *(uint32_t*)(smem + SM_HHI + row*528 + col*2) = pack_bf16(hh0, hh1);
                    *(uint32_t*)(smem + SM_HLO + row*528 + col*2) = pack_bf16(ll0, ll1);
                }
        __syncthreads();

        // ------------- GEMM2: logits += H[128][256] @ w2t chunk -------------
        for (int kc2 = 0; kc2 < 4; kc2++) {
            __syncthreads();
            {   // W2 chunk [64 n2][64 k] hi/lo
                int n2 = tid >> 3, seg = tid & 7;
                *(uint4*)(smem + SM_W2HI + n2*144 + seg*16) =
                    *(const uint4*)(g_w2t_hi + (size_t)n2*512 + nc*256 + kc2*64 + seg*8);
                *(uint4*)(smem + SM_W2LO + n2*144 + seg*16) =
                    *(const uint4*)(g_w2t_lo + (size_t)n2*512 + nc*256 + kc2*64 + seg*8);
            }
            __syncthreads();
            const uint32_t hsrc[3]  = {SM_HHI,  SM_HHI,  SM_HLO};
            const uint32_t w2src[3] = {SM_W2HI, SM_W2LO, SM_W2HI};
            #pragma unroll
            for (int p = 0; p < 3; p++) {
                uint32_t hb  = sb + hsrc[p]  + aoffH + (uint32_t)(wm*32*528) + (uint32_t)(kc2*128);
                uint32_t w2b = sb + w2src[p] + boff2 + (uint32_t)(wn*16*144);
                #pragma unroll
                for (int ks = 0; ks < 4; ks++) {
                    uint32_t a0[4], a1[4];
                    ldsm_x4(a0, hb + ks*32);
                    ldsm_x4(a1, hb + 16*528 + ks*32);
                    #pragma unroll
                    for (int nt = 0; nt < 2; nt++) {
                        uint32_t bf[2];
                        ldsm_x2(bf, w2b + nt*8*144 + ks*32);
                        mma_bf16(acc2[0][nt], a0, bf);
                        mma_bf16(acc2[1][nt], a1, bf);
                    }
                }
            }
        }
    }

    // ---------------- store logits (+b2) ----------------
    #pragma unroll
    for (int mt = 0; mt < 2; mt++)
        #pragma unroll
        for (int nt = 0; nt < 2; nt++)
            #pragma unroll
            for (int h = 0; h < 2; h++) {
                int row = wm*32 + mt*16 + h*8 + qrow;
                int col = wn*16 + nt*8 + qcol;
                float2 v;
                v.x = acc2[mt][nt][h*2+0] + b2s[col];
                v.y = acc2[mt][nt][h*2+1] + b2s[col+1];
                *(float2*)(g_logits + (t0 + row)*NN + col) = v;
            }
}

// =====================================================================
// K2: per-(b,n) online max & sumexp over T   (grid 32, 256 thr)
// =====================================================================
__global__ void __launch_bounds__(256) k_stats()
{
    const int b = blockIdx.x, tid = threadIdx.x;
    const int n = tid & 63, tg = tid >> 6;
    const float* base = g_logits + (size_t)b*TT*NN;
    float m = -1e30f, s = 0.0f;
    for (int t = tg; t < TT; t += 4) {
        float v = base[(size_t)t*NN + n];
        if (v <= m) s += __expf(v - m);
        else { s = s * __expf(m - v) + 1.0f; m = v; }
    }
    __shared__ float sm_m[4][64], sm_s[4][64];
    sm_m[tg][n] = m; sm_s[tg][n] = s;
    __syncthreads();
    if (tid < 64) {
        float M = sm_m[0][tid];
        #pragma unroll
        for (int i = 1; i < 4; i++) M = fmaxf(M, sm_m[i][tid]);
        float S = 0.0f;
        #pragma unroll
        for (int i = 0; i < 4; i++) S += sm_s[i][tid] * __expf(sm_m[i][tid] - M);
        g_m[b*NN + tid] = M;
        g_rs[b*NN + tid] = 1.0f / S;
    }
}

// =====================================================================
// K3: feat_raw[b,n,d] = (1/S) * sum_t exp(logit - m) * input[b,t,d]
// grid (4, 32): 64x128 output tile, K=4096.  256 thr.
// =====================================================================
__global__ void __launch_bounds__(256) k_feat(const float* __restrict__ input)
{
    __shared__ float Ps[32*64];
    __shared__ float Xs[32*128];
    __shared__ float ms[64], rss[64];

    const int b = blockIdx.y;
    const int d0 = blockIdx.x * 128;
    const int tid = threadIdx.x;
    if (tid < 64) { ms[tid] = g_m[b*NN + tid]; rss[tid] = g_rs[b*NN + tid]; }

    const int ty = tid >> 4, tx = tid & 15;
    const int n0 = ty * 4, c0 = tx * 8;
    float acc[4][8] = {};

    const float* L = g_logits + (size_t)b*TT*NN;
    const float* X = input + (size_t)b*TT*DD;

    for (int kt = 0; kt < 128; kt++) {
        const int t0 = kt * 32;
        __syncthreads();
        #pragma unroll
        for (int i = 0; i < 8; i++) {
            int idx = tid + 256*i;
            int t = idx >> 6, n = idx & 63;
            Ps[t*64 + n] = __expf(L[(size_t)(t0+t)*NN + n] - ms[n]);
        }
        #pragma unroll
        for (int i = 0; i < 4; i++) {
            int idx = tid + 256*i;
            int t = idx >> 5, c4 = idx & 31;
            ((float4*)Xs)[idx] = *(const float4*)(X + (size_t)(t0+t)*DD + d0 + c4*4);
        }
        __syncthreads();
        #pragma unroll 8
        for (int kk = 0; kk < 32; kk++) {
            float a0 = Ps[kk*64 + n0+0];
            float a1 = Ps[kk*64 + n0+1];
            float a2 = Ps[kk*64 + n0+2];
            float a3 = Ps[kk*64 + n0+3];
            float4 b0 = *(const float4*)(Xs + kk*128 + c0);
            float4 b1v = *(const float4*)(Xs + kk*128 + c0 + 4);
            acc[0][0]+=a0*b0.x; acc[0][1]+=a0*b0.y; acc[0][2]+=a0*b0.z; acc[0][3]+=a0*b0.w;
            acc[0][4]+=a0*b1v.x; acc[0][5]+=a0*b1v.y; acc[0][6]+=a0*b1v.z; acc[0][7]+=a0*b1v.w;
            acc[1][0]+=a1*b0.x; acc[1][1]+=a1*b0.y; acc[1][2]+=a1*b0.z; acc[1][3]+=a1*b0.w;
            acc[1][4]+=a1*b1v.x; acc[1][5]+=a1*b1v.y; acc[1][6]+=a1*b1v.z; acc[1][7]+=a1*b1v.w;
            acc[2][0]+=a2*b0.x; acc[2][1]+=a2*b0.y; acc[2][2]+=a2*b0.z; acc[2][3]+=a2*b0.w;
            acc[2][4]+=a2*b1v.x; acc[2][5]+=a2*b1v.y; acc[2][6]+=a2*b1v.z; acc[2][7]+=a2*b1v.w;
            acc[3][0]+=a3*b0.x; acc[3][1]+=a3*b0.y; acc[3][2]+=a3*b0.z; acc[3][3]+=a3*b0.w;
            acc[3][4]+=a3*b1v.x; acc[3][5]+=a3*b1v.y; acc[3][6]+=a3*b1v.z; acc[3][7]+=a3*b1v.w;
        }
    }
    #pragma unroll
    for (int i = 0; i < 4; i++) {
        float r = rss[n0+i];
        float* dst = g_featraw + (size_t)(b*NN + n0+i)*DD + d0 + c0;
        float4 o0, o1;
        o0.x = acc[i][0]*r; o0.y = acc[i][1]*r; o0.z = acc[i][2]*r; o0.w = acc[i][3]*r;
        o1.x = acc[i][4]*r; o1.y = acc[i][5]*r; o1.z = acc[i][6]*r; o1.w = acc[i][7]*r;
        *(float4*)dst = o0;
        *(float4*)(dst + 4) = o1;
    }
}

// =====================================================================
// LayerNorm helper: one warp per 512-wide row
// =====================================================================
__device__ __forceinline__ void ln_row(const float* __restrict__ src,
                                       float* __restrict__ dst,
                                       const float* __restrict__ gamma,
                                       const float* __restrict__ beta,
                                       int lane)
{
    float4 v[4];
    float s = 0.0f, sq = 0.0f;
    #pragma unroll
    for (int i = 0; i < 4; i++) {
        v[i] = *(const float4*)(src + i*128 + lane*4);
        s  += v[i].x + v[i].y + v[i].z + v[i].w;
        sq += v[i].x*v[i].x + v[i].y*v[i].y + v[i].z*v[i].z + v[i].w*v[i].w;
    }
    #pragma unroll
    for (int o = 16; o > 0; o >>= 1) {
        s  += __shfl_xor_sync(0xffffffffu, s, o);
        sq += __shfl_xor_sync(0xffffffffu, sq, o);
    }
    float mean = s * (1.0f/512.0f);
    float var  = sq * (1.0f/512.0f) - mean*mean;
    float inv  = rsqrtf(var + 1e-5f);
    #pragma unroll
    for (int i = 0; i < 4; i++) {
        int c = i*128 + lane*4;
        float4 g4 = *(const float4*)(gamma + c);
        float4 b4 = *(const float4*)(beta + c);
        float4 o;
        o.x = (v[i].x - mean)*inv*g4.x + b4.x;
        o.y = (v[i].y - mean)*inv*g4.y + b4.y;
        o.z = (v[i].z - mean)*inv*g4.z + b4.z;
        o.w = (v[i].w - mean)*inv*g4.w + b4.w;
        *(float4*)(dst + c) = o;
    }
}

// K4: LN1(feat_raw) -> g_U segment 0.  grid 256, 256 thr
__global__ void __launch_bounds__(256) k_ln1(const float* __restrict__ g,
                                             const float* __restrict__ be)
{
    int warp = threadIdx.x >> 5, lane = threadIdx.x & 31;
    int row = blockIdx.x * 8 + warp;
    ln_row(g_featraw + (size_t)row*DD, g_U + (size_t)row*2048, g, be, lane);
}

// =====================================================================
// K5: per-batch CQA core. grid 32, 256 thr, dyn smem 214016 B
// =====================================================================
#define QS_STRIDE 516
#define K5_SMEM ((LL*QS_STRIDE + NN*DD + 2*NN*33) * 4)
__global__ void __launch_bounds__(256) k_cqa(const float* __restrict__ query)
{
    extern __shared__ float sm[];
    float* qs = sm;                         // [32][516]  (later reused for M)
    float* fs = qs + LL*QS_STRIDE;          // [64][512]
    float* s0 = fs + NN*DD;                 // [64][33]  sim -> sim_c
    float* sr = s0 + NN*33;                 // [64][33]  sim_r

    const int b = blockIdx.x, tid = threadIdx.x;

    for (int i = tid; i < LL*128; i += 256) {
        int l = i >> 7, c4 = i & 127;
        *(float4*)(qs + l*QS_STRIDE + c4*4) =
            *(const float4*)(query + (size_t)(b*LL + l)*DD + c4*4);
    }
    for (int i = tid; i < NN*128; i += 256) {
        int n = i >> 7, c4 = i & 127;
        *(float4*)(fs + n*DD + c4*4) =
            *(const float4*)(g_U + (size_t)(b*NN + n)*2048 + c4*4);
    }
    __syncthreads();

    {
        const int l = tid & 31, ng = tid >> 5;
        #pragma unroll
        for (int j = 0; j < 8; j++) {
            int n = ng + 8*j;
            float s = 0.0f;
            #pragma unroll 4
            for (int k = 0; k < DD; k++) s += fs[n*DD + k] * qs[l*QS_STRIDE + k];
            s0[n*33 + l] = s;
        }
    }
    __syncthreads();
    if (tid < 64) {
        int n = tid;
        float M = -1e30f;
        for (int l = 0; l < 32; l++) M = fmaxf(M, s0[n*33 + l]);
        float S = 0.0f;
        for (int l = 0; l < 32; l++) S += __expf(s0[n*33 + l] - M);
        float inv = 1.0f / S;
        for (int l = 0; l < 32; l++) sr[n*33 + l] = __expf(s0[n*33 + l] - M) * inv;
    }
    __syncthreads();
    if (tid < 32) {
        int l = tid;
        float M = -1e30f;
        for (int n = 0; n < 64; n++) M = fmaxf(M, s0[n*33 + l]);
        float S = 0.0f;
        for (int n = 0; n < 64; n++) S += __expf(s0[n*33 + l] - M);
        float inv = 1.0f / S;
        for (int n = 0; n < 64; n++) s0[n*33 + l] = __expf(s0[n*33 + l] - M) * inv;
    }
    __syncthreads();

    for (int i = tid; i < NN*128; i += 256) {
        int n = i >> 7, c4 = i & 127, d = c4*4;
        float4 a = {0,0,0,0};
        #pragma unroll
        for (int l = 0; l < 32; l++) {
            float w = sr[n*33 + l];
            float4 qv = *(const float4*)(qs + l*QS_STRIDE + d);
            a.x += w*qv.x; a.y += w*qv.y; a.z += w*qv.z; a.w += w*qv.w;
        }
        float4 f = *(const float4*)(fs + n*DD + d);
        float* dst = g_U + (size_t)(b*NN + n)*2048;
        *(float4*)(dst + 512 + d) = a;
        float4 e3 = {f.x*a.x, f.y*a.y, f.z*a.z, f.w*a.w};
        *(float4*)(dst + 1024 + d) = e3;
    }
    __syncthreads();

    for (int i = tid; i < LL*128; i += 256) {
        int l = i >> 7, c4 = i & 127, d = c4*4;
        float4 m = {0,0,0,0};
        #pragma unroll 8
        for (int n = 0; n < 64; n++) {
            float w = s0[n*33 + l];
            float4 fv = *(const float4*)(fs + n*DD + d);
            m.x += w*fv.x; m.y += w*fv.y; m.z += w*fv.z; m.w += w*fv.w;
        }
        *(float4*)(qs + l*QS_STRIDE + d) = m;
    }
    __syncthreads();

    for (int i = tid; i < NN*128; i += 256) {
        int n = i >> 7, c4 = i & 127, d = c4*4;
        float4 bm = {0,0,0,0};
        #pragma unroll
        for (int l = 0; l < 32; l++) {
            float w = sr[n*33 + l];
            float4 mv = *(const float4*)(qs + l*QS_STRIDE + d);
            bm.x += w*mv.x; bm.y += w*mv.y; bm.z += w*mv.z; bm.w += w*mv.w;
        }
        float4 f = *(const float4*)(fs + n*DD + d);
        float4 e4 = {f.x*bm.x, f.y*bm.y, f.z*bm.z, f.w*bm.w};
        *(float4*)(g_U + (size_t)(b*NN + n)*2048 + 1536 + d) = e4;
    }
}

// =====================================================================
// K6: cat = U[2048,2048] @ [wf1;wf2;wf3;wf4] + (bf1+bf2+bf3+bf4)
// =====================================================================
__global__ void __launch_bounds__(256) k_headgemm(
    const float* __restrict__ wf1, const float* __restrict__ wf2,
    const float* __restrict__ wf3, const float* __restrict__ wf4,
    const float* __restrict__ bf1, const float* __restrict__ bf2,
    const float* __restrict__ bf3, const float* __restrict__ bf4)
{
    __shared__ float Us[64*64];
    __shared__ float Ws[64*64];
    __shared__ float bsum[64];

    const int n0 = blockIdx.x * 64;
    const int m0 = blockIdx.y * 64;
    const int tid = threadIdx.x;
    if (tid < 64) bsum[tid] = bf1[n0+tid] + bf2[n0+tid] + bf3[n0+tid] + bf4[n0+tid];

    const int ty = tid >> 4, tx = tid & 15;
    const int r0 = ty * 4, c0 = tx * 4;
    float acc[4][4] = {};

    for (int kt = 0; kt < 32; kt++) {
        __syncthreads();
        const float* wseg = (kt < 8) ? wf1 : (kt < 16) ? wf2 : (kt < 24) ? wf3 : wf4;
        const int rbase = (kt & 7) * 64;
        #pragma unroll
        for (int i = 0; i < 4; i++) {
            int idx = tid + 256*i;
            int r = idx >> 4, c4 = (idx & 15) * 4;
            ((float4*)Us)[idx] = *(const float4*)(g_U + (size_t)(m0+r)*2048 + kt*64 + c4);
            ((float4*)Ws)[idx] = *(const float4*)(wseg + (size_t)(rbase+r)*DD + n0 + c4);
        }
        __syncthreads();
        #pragma unroll 8
        for (int kk = 0; kk < 64; kk++) {
            float a0 = Us[(r0+0)*64 + kk];
            float a1 = Us[(r0+1)*64 + kk];
            float a2 = Us[(r0+2)*64 + kk];
            float a3 = Us[(r0+3)*64 + kk];
            float4 bv = *(const float4*)(Ws + kk*64 + c0);
            acc[0][0]+=a0*bv.x; acc[0][1]+=a0*bv.y; acc[0][2]+=a0*bv.z; acc[0][3]+=a0*bv.w;
            acc[1][0]+=a1*bv.x; acc[1][1]+=a1*bv.y; acc[1][2]+=a1*bv.z; acc[1][3]+=a1*bv.w;
            acc[2][0]+=a2*bv.x; acc[2][1]+=a2*bv.y; acc[2][2]+=a2*bv.z; acc[2][3]+=a2*bv.w;
            acc[3][0]+=a3*bv.x; acc[3][1]+=a3*bv.y; acc[3][2]+=a3*bv.z; acc[3][3]+=a3*bv.w;
        }
    }
    #pragma unroll
    for (int i = 0; i < 4; i++) {
        float4 o;
        o.x = acc[i][0] + bsum[c0+0];
        o.y = acc[i][1] + bsum[c0+1];
        o.z = acc[i][2] + bsum[c0+2];
        o.w = acc[i][3] + bsum[c0+3];
        *(float4*)(g_cat + (size_t)(m0+r0+i)*DD + n0 + c0) = o;
    }
}

// K7: LN2(cat) -> d_out.  grid 256, 256 thr
__global__ void __launch_bounds__(256) k_ln2(const float* __restrict__ g,
                                             const float* __restrict__ be,
                                             float* __restrict__ out)
{
    int warp = threadIdx.x >> 5, lane = threadIdx.x & 31;
    int row = blockIdx.x * 8 + warp;
    ln_row(g_cat + (size_t)row*DD, out + (size_t)row*DD, g, be, lane);
}

// =====================================================================
extern "C" void kernel_launch(void* const* d_in, const int* in_sizes, int n_in,
                              void* d_out, int out_size)
{
    const float* input = (const float*)d_in[0];
    const float* query = (const float*)d_in[1];
    const float* w1    = (const float*)d_in[2];
    const float* b1    = (const float*)d_in[3];
    const float* w2    = (const float*)d_in[4];
    const float* b2    = (const float*)d_in[5];
    const float* ln1g  = (const float*)d_in[6];
    const float* ln1b  = (const float*)d_in[7];
    const float* wf1   = (const float*)d_in[8];
    const float* bf1   = (const float*)d_in[9];
    const float* wf2   = (const float*)d_in[10];
    const float* bf2   = (const float*)d_in[11];
    const float* wf3   = (const float*)d_in[12];
    const float* bf3   = (const float*)d_in[13];
    const float* wf4   = (const float*)d_in[14];
    const float* bf4   = (const float*)d_in[15];
    const float* ln2g  = (const float*)d_in[16];
    const float* ln2b  = (const float*)d_in[17];
    float* out = (float*)d_out;

    cudaFuncSetAttribute(k_logits_tc, cudaFuncAttributeMaxDynamicSharedMemorySize, K1TC_SMEM);
    cudaFuncSetAttribute(k_cqa,       cudaFuncAttributeMaxDynamicSharedMemorySize, K5_SMEM);

    k_prep<<<576, 256>>>(w1, w2);
    k_logits_tc<<<BB*TT/128, 512, K1TC_SMEM>>>(input, b1, b2);
    k_stats<<<BB, 256>>>();
    k_feat<<<dim3(4, BB), 256>>>(input);
    k_ln1<<<ROWS/8, 256>>>(ln1g, ln1b);
    k_cqa<<<BB, 256, K5_SMEM>>>(query);
    k_headgemm<<<dim3(8, 32), 256>>>(wf1, wf2, wf3, wf4, bf1, bf2, bf3, bf4);
    k_ln2<<<ROWS/8, 256>>>(ln2g, ln2b, out);
}

// round 8
// speedup vs baseline: 1.9093x; 1.0150x over previous
#include <cuda_runtime.h>
#include <cuda_bf16.h>
#include <cstdint>
#include <cmath>

// Problem dims (fixed per reference setup_inputs)
#define BB 32
#define TT 4096
#define LL 32
#define DD 512
#define NN 64
#define ROWS (BB*NN)          // 2048

// ---------------- scratch (device globals; no allocs allowed) ----------------
__device__ float g_logits[BB*TT*NN];        // [B*T][64]   32 MB
__device__ float g_m[ROWS];
__device__ float g_rs[ROWS];
__device__ float g_part[4*ROWS*DD];         // t-split partial feat sums, 16 MB
__device__ float g_U[ROWS*2048];
__device__ float g_cat[ROWS*DD];
// split-bf16 transposed weights (K-major rows)
__device__ __nv_bfloat16 g_w1t_hi[DD*DD];   // [n=512][k=512]
__device__ __nv_bfloat16 g_w1t_lo[DD*DD];
__device__ __nv_bfloat16 g_w2t_hi[NN*DD];   // [n=64][k=512]
__device__ __nv_bfloat16 g_w2t_lo[NN*DD];
__device__ __nv_bfloat16 g_wft_hi[DD*2048]; // [n=512][k=2048]  (wf1..4 stacked in k)
__device__ __nv_bfloat16 g_wft_lo[DD*2048];

__device__ __forceinline__ float gelu_exact(float x) {
    return 0.5f * x * (1.0f + erff(x * 0.70710678118654752f));
}

// ===================== mma.sync / ldmatrix helpers (sm_80+ PTX) ==============
__device__ __forceinline__ uint32_t smem_u32(const void* p) {
    uint32_t a;
    asm("{ .reg .u64 t; cvta.to.shared.u64 t, %1; cvt.u32.u64 %0, t; }" : "=r"(a) : "l"(p));
    return a;
}
__device__ __forceinline__ void ldsm_x4(uint32_t r[4], uint32_t addr) {
    asm volatile("ldmatrix.sync.aligned.m8n8.x4.shared.b16 {%0,%1,%2,%3}, [%4];"
        : "=r"(r[0]), "=r"(r[1]), "=r"(r[2]), "=r"(r[3]) : "r"(addr));
}
__device__ __forceinline__ void ldsm_x2(uint32_t r[2], uint32_t addr) {
    asm volatile("ldmatrix.sync.aligned.m8n8.x2.shared.b16 {%0,%1}, [%2];"
        : "=r"(r[0]), "=r"(r[1]) : "r"(addr));
}
__device__ __forceinline__ void mma_bf16(float* d, const uint32_t* a, const uint32_t* b) {
    asm volatile("mma.sync.aligned.m16n8k16.row.col.f32.bf16.bf16.f32 "
        "{%0,%1,%2,%3}, {%4,%5,%6,%7}, {%8,%9}, {%0,%1,%2,%3};"
        : "+f"(d[0]), "+f"(d[1]), "+f"(d[2]), "+f"(d[3])
        : "r"(a[0]), "r"(a[1]), "r"(a[2]), "r"(a[3]), "r"(b[0]), "r"(b[1]));
}
__device__ __forceinline__ uint32_t pack_bf16(__nv_bfloat16 a, __nv_bfloat16 b) {
    return ((uint32_t)__bfloat16_as_ushort(b) << 16) | (uint32_t)__bfloat16_as_ushort(a);
}
__device__ __forceinline__ void split_bf16(float x, __nv_bfloat16& h, __nv_bfloat16& l) {
    h = __float2bfloat16(x);
    l = __float2bfloat16(x - __bfloat162float(h));
}

// =====================================================================
// K0: coalesced transpose + split.  src [512 k][ncols n] fp32 ->
// dst_hi/lo [n][dstride] bf16 at column offset doff.
// sel: 0=w1, 1=w2, 2..5=wf1..4
// grid (ncols/32, 16), 256 thr
// =====================================================================
__global__ void __launch_bounds__(256) k_tsplit(const float* __restrict__ src, int sel)
{
    __shared__ float tile[32][33];
    int ncols, dstride, doff;
    __nv_bfloat16 *dh, *dl;
    if (sel == 0)      { ncols = 512; dstride = 512;  doff = 0; dh = g_w1t_hi; dl = g_w1t_lo; }
    else if (sel == 1) { ncols = 64;  dstride = 512;  doff = 0; dh = g_w2t_hi; dl = g_w2t_lo; }
    else               { ncols = 512; dstride = 2048; doff = (sel-2)*512; dh = g_wft_hi; dl = g_wft_lo; }

    const int n0 = blockIdx.x * 32, k0 = blockIdx.y * 32;
    const int tx = threadIdx.x & 31, ty = threadIdx.x >> 5;
    #pragma unroll
    for (int i = 0; i < 4; i++) {
        int r = ty + i*8;
        tile[r][tx] = src[(size_t)(k0 + r)*ncols + n0 + tx];
    }
    __syncthreads();
    #pragma unroll
    for (int i = 0; i < 4; i++) {
        int r = ty + i*8;
        float x = tile[tx][r];
        __nv_bfloat16 h, l; split_bf16(x, h, l);
        size_t o = (size_t)(n0 + r)*dstride + doff + k0 + tx;
        dh[o] = h; dl[o] = l;
    }
}

// =====================================================================
// K1: split-bf16 mma.sync  logits = GELU(X@w1+b1)@w2 + b2
// grid 1024 (128 tokens/CTA), 512 thr, dyn smem 198912 B
// =====================================================================
#define SM_XHI   0
#define SM_XLO   10240
#define SM_W1HI  20480
#define SM_W1LO  40960
#define SM_W2HI  0            // reuses X/W1 region during GEMM2
#define SM_W2LO  9216
#define SM_HHI   61440
#define SM_HLO   129024
#define SM_B1    196608
#define SM_B2    198656
#define K1TC_SMEM 198912

__global__ void __launch_bounds__(512, 1) k_logits_tc(
    const float* __restrict__ input,
    const float* __restrict__ b1, const float* __restrict__ b2)
{
    extern __shared__ char smem[];
    const uint32_t sb = smem_u32(smem);
    const int tid = threadIdx.x;
    const int wid = tid >> 5, lane = tid & 31;
    const int wm = wid & 3, wn = wid >> 2;       // warp grid 4(M) x 4(N)
    const size_t t0 = (size_t)blockIdx.x * 128;

    float* b1s = (float*)(smem + SM_B1);
    float* b2s = (float*)(smem + SM_B2);
    b1s[tid & 511] = b1[tid & 511];
    if (tid < 64) b2s[tid] = b2[tid];

    const uint32_t aoffX = (uint32_t)((lane & 15) * 80  + (lane >> 4) * 16);
    const uint32_t boffW = (uint32_t)((lane & 7)  * 80  + ((lane >> 3) & 1) * 16);
    const uint32_t aoffH = (uint32_t)((lane & 15) * 528 + (lane >> 4) * 16);
    const uint32_t boff2 = (uint32_t)((lane & 7)  * 144 + ((lane >> 3) & 1) * 16);
    const int qrow = lane >> 2, qcol = (lane & 3) * 2;

    float acc2[2][2][4];
    #pragma unroll
    for (int i = 0; i < 2; i++)
        #pragma unroll
        for (int j = 0; j < 2; j++)
            #pragma unroll
            for (int k = 0; k < 4; k++) acc2[i][j][k] = 0.0f;

    for (int nc = 0; nc < 2; nc++) {
        float acc[2][8][4];
        #pragma unroll
        for (int i = 0; i < 2; i++)
            #pragma unroll
            for (int j = 0; j < 8; j++)
                #pragma unroll
                for (int k = 0; k < 4; k++) acc[i][j][k] = 0.0f;

        // ---------------- GEMM1: K=512 in 16 chunks of 32 ----------------
        for (int kc = 0; kc < 16; kc++) {
            __syncthreads();
            {   // X chunk [128 tok][32 k] fp32 -> bf16 hi/lo
                int row = tid >> 2, seg = tid & 3;
                const float* src = input + (t0 + row)*DD + kc*32 + seg*8;
                float4 v0 = *(const float4*)src;
                float4 v1 = *(const float4*)(src + 4);
                __nv_bfloat16 h[8], l[8];
                split_bf16(v0.x, h[0], l[0]); split_bf16(v0.y, h[1], l[1]);
                split_bf16(v0.z, h[2], l[2]); split_bf16(v0.w, h[3], l[3]);
                split_bf16(v1.x, h[4], l[4]); split_bf16(v1.y, h[5], l[5]);
                split_bf16(v1.z, h[6], l[6]); split_bf16(v1.w, h[7], l[7]);
                uint4 hp = { pack_bf16(h[0],h[1]), pack_bf16(h[2],h[3]),
                             pack_bf16(h[4],h[5]), pack_bf16(h[6],h[7]) };
                uint4 lp = { pack_bf16(l[0],l[1]), pack_bf16(l[2],l[3]),
                             pack_bf16(l[4],l[5]), pack_bf16(l[6],l[7]) };
                *(uint4*)(smem + SM_XHI + row*80 + seg*16) = hp;
                *(uint4*)(smem + SM_XLO + row*80 + seg*16) = lp;
            }
            {   // W1 chunk [256 n][32 k] hi/lo
                int n = tid >> 1, part = tid & 1;
                const uint4* sh = (const uint4*)(g_w1t_hi + (size_t)(nc*256 + n)*512 + kc*32 + part*16);
                const uint4* sl = (const uint4*)(g_w1t_lo + (size_t)(nc*256 + n)*512 + kc*32 + part*16);
                uint4 h0 = sh[0], h1 = sh[1];
                uint4 l0 = sl[0], l1 = sl[1];
                char* dh = smem + SM_W1HI + n*80 + part*32;
                char* dl = smem + SM_W1LO + n*80 + part*32;
                *(uint4*)dh = h0; *(uint4*)(dh + 16) = h1;
                *(uint4*)dl = l0; *(uint4*)(dl + 16) = l1;
            }
            __syncthreads();
            const uint32_t xsrc[3] = {SM_XHI, SM_XHI, SM_XLO};
            const uint32_t wsrc[3] = {SM_W1HI, SM_W1LO, SM_W1HI};
            #pragma unroll
            for (int p = 0; p < 3; p++) {
                uint32_t xb = sb + xsrc[p] + aoffX + (uint32_t)(wm*32*80);
                uint32_t wb = sb + wsrc[p] + boffW + (uint32_t)(wn*64*80);
                #pragma unroll
                for (int ks = 0; ks < 2; ks++) {
                    uint32_t a0[4], a1[4];
                    ldsm_x4(a0, xb + ks*32);
                    ldsm_x4(a1, xb + 16*80 + ks*32);
                    #pragma unroll
                    for (int nt = 0; nt < 8; nt++) {
                        uint32_t bf[2];
                        ldsm_x2(bf, wb + nt*8*80 + ks*32);
                        mma_bf16(acc[0][nt], a0, bf);
                        mma_bf16(acc[1][nt], a1, bf);
                    }
                }
            }
        }

        // ------------- epilogue: bias + GELU + split -> H (SMEM) -------------
        __syncthreads();
        #pragma unroll
        for (int mt = 0; mt < 2; mt++)
            #pragma unroll
            for (int nt = 0; nt < 8; nt++)
                #pragma unroll
                for (int h = 0; h < 2; h++) {
                    int row = wm*32 + mt*16 + h*8 + qrow;
                    int col = wn*64 + nt*8 + qcol;
                    float x0 = acc[mt][nt][h*2+0] + b1s[nc*256 + col];
                    float x1 = acc[mt][nt][h*2+1] + b1s[nc*256 + col + 1];
                    float g0 = gelu_exact(x0), g1 = gelu_exact(x1);
                    __nv_bfloat16 hh0, ll0, hh1, ll1;
                    split_bf16(g0, hh0, ll0); split_bf16(g1, hh1, ll1);
                    *(uint32_t*)(smem + SM_HHI + row*528 + col*2) = pack_bf16(hh0, hh1);
                    *(uint32_t*)(smem + SM_HLO + row*528 + col*2) = pack_bf16(ll0, ll1);
                }
        __syncthreads();

        // ------------- GEMM2: logits += H[128][256] @ w2t chunk -------------
        for (int kc2 = 0; kc2 < 4; kc2++) {
            __syncthreads();
            {   // W2 chunk [64 n2][64 k] hi/lo
                int n2 = tid >> 3, seg = tid & 7;
                *(uint4*)(smem + SM_W2HI + n2*144 + seg*16) =
                    *(const uint4*)(g_w2t_hi + (size_t)n2*512 + nc*256 + kc2*64 + seg*8);
                *(uint4*)(smem + SM_W2LO + n2*144 + seg*16) =
                    *(const uint4*)(g_w2t_lo + (size_t)n2*512 + nc*256 + kc2*64 + seg*8);
            }
            __syncthreads();
            const uint32_t hsrc[3]  = {SM_HHI,  SM_HHI,  SM_HLO};
            const uint32_t w2src[3] = {SM_W2HI, SM_W2LO, SM_W2HI};
            #pragma unroll
            for (int p = 0; p < 3; p++) {
                uint32_t hb  = sb + hsrc[p]  + aoffH + (uint32_t)(wm*32*528) + (uint32_t)(kc2*128);
                uint32_t w2b = sb + w2src[p] + boff2 + (uint32_t)(wn*16*144);
                #pragma unroll
                for (int ks = 0; ks < 4; ks++) {
                    uint32_t a0[4], a1[4];
                    ldsm_x4(a0, hb + ks*32);
                    ldsm_x4(a1, hb + 16*528 + ks*32);
                    #pragma unroll
                    for (int nt = 0; nt < 2; nt++) {
                        uint32_t bf[2];
                        ldsm_x2(bf, w2b + nt*8*144 + ks*32);
                        mma_bf16(acc2[0][nt], a0, bf);
                        mma_bf16(acc2[1][nt], a1, bf);
                    }
                }
            }
        }
    }

    // ---------------- store logits (+b2) ----------------
    #pragma unroll
    for (int mt = 0; mt < 2; mt++)
        #pragma unroll
        for (int nt = 0; nt < 2; nt++)
            #pragma unroll
            for (int h = 0; h < 2; h++) {
                int row = wm*32 + mt*16 + h*8 + qrow;
                int col = wn*16 + nt*8 + qcol;
                float2 v;
                v.x = acc2[mt][nt][h*2+0] + b2s[col];
                v.y = acc2[mt][nt][h*2+1] + b2s[col+1];
                *(float2*)(g_logits + (t0 + row)*NN + col) = v;
            }
}

// =====================================================================
// K2: per-(b,n) online max & sumexp over T   (grid 32, 256 thr)
// =====================================================================
__global__ void __launch_bounds__(256) k_stats()
{
    const int b = blockIdx.x, tid = threadIdx.x;
    const int n = tid & 63, tg = tid >> 6;
    const float* base = g_logits + (size_t)b*TT*NN;
    float m = -1e30f, s = 0.0f;
    for (int t = tg; t < TT; t += 4) {
        float v = base[(size_t)t*NN + n];
        if (v <= m) s += __expf(v - m);
        else { s = s * __expf(m - v) + 1.0f; m = v; }
    }
    __shared__ float sm_m[4][64], sm_s[4][64];
    sm_m[tg][n] = m; sm_s[tg][n] = s;
    __syncthreads();
    if (tid < 64) {
        float M = sm_m[0][tid];
        #pragma unroll
        for (int i = 1; i < 4; i++) M = fmaxf(M, sm_m[i][tid]);
        float S = 0.0f;
        #pragma unroll
        for (int i = 0; i < 4; i++) S += sm_s[i][tid] * __expf(sm_m[i][tid] - M);
        g_m[b*NN + tid] = M;
        g_rs[b*NN + tid] = 1.0f / S;
    }
}

// =====================================================================
// K3: partial feat sums over 1024-token slabs.
// grid (4 d-tiles, 32 b, 4 t-splits), 256 thr.
// g_part[ts][b*64+n][d] = sum_{t in slab} exp(logit-m) * input[t][d]
// =====================================================================
__global__ void __launch_bounds__(256) k_feat(const float* __restrict__ input)
{
    __shared__ float Ps[32*64];
    __shared__ float Xs[32*128];
    __shared__ float ms[64];

    const int b = blockIdx.y;
    const int d0 = blockIdx.x * 128;
    const int ts = blockIdx.z;
    const int tid = threadIdx.x;
    if (tid < 64) ms[tid] = g_m[b*NN + tid];

    const int ty = tid >> 4, tx = tid & 15;
    const int n0 = ty * 4, c0 = tx * 8;
    float acc[4][8] = {};

    const float* L = g_logits + (size_t)b*TT*NN;
    const float* X = input + (size_t)b*TT*DD;

    for (int kt = 0; kt < 32; kt++) {
        const int t0 = (ts*32 + kt) * 32;
        __syncthreads();
        #pragma unroll
        for (int i = 0; i < 8; i++) {
            int idx = tid + 256*i;
            int t = idx >> 6, n = idx & 63;
            Ps[t*64 + n] = __expf(L[(size_t)(t0+t)*NN + n] - ms[n]);
        }
        #pragma unroll
        for (int i = 0; i < 4; i++) {
            int idx = tid + 256*i;
            int t = idx >> 5, c4 = idx & 31;
            ((float4*)Xs)[idx] = *(const float4*)(X + (size_t)(t0+t)*DD + d0 + c4*4);
        }
        __syncthreads();
        #pragma unroll 8
        for (int kk = 0; kk < 32; kk++) {
            float a0 = Ps[kk*64 + n0+0];
            float a1 = Ps[kk*64 + n0+1];
            float a2 = Ps[kk*64 + n0+2];
            float a3 = Ps[kk*64 + n0+3];
            float4 b0 = *(const float4*)(Xs + kk*128 + c0);
            float4 b1v = *(const float4*)(Xs + kk*128 + c0 + 4);
            acc[0][0]+=a0*b0.x; acc[0][1]+=a0*b0.y; acc[0][2]+=a0*b0.z; acc[0][3]+=a0*b0.w;
            acc[0][4]+=a0*b1v.x; acc[0][5]+=a0*b1v.y; acc[0][6]+=a0*b1v.z; acc[0][7]+=a0*b1v.w;
            acc[1][0]+=a1*b0.x; acc[1][1]+=a1*b0.y; acc[1][2]+=a1*b0.z; acc[1][3]+=a1*b0.w;
            acc[1][4]+=a1*b1v.x; acc[1][5]+=a1*b1v.y; acc[1][6]+=a1*b1v.z; acc[1][7]+=a1*b1v.w;
            acc[2][0]+=a2*b0.x; acc[2][1]+=a2*b0.y; acc[2][2]+=a2*b0.z; acc[2][3]+=a2*b0.w;
            acc[2][4]+=a2*b1v.x; acc[2][5]+=a2*b1v.y; acc[2][6]+=a2*b1v.z; acc[2][7]+=a2*b1v.w;
            acc[3][0]+=a3*b0.x; acc[3][1]+=a3*b0.y; acc[3][2]+=a3*b0.z; acc[3][3]+=a3*b0.w;
            acc[3][4]+=a3*b1v.x; acc[3][5]+=a3*b1v.y; acc[3][6]+=a3*b1v.z; acc[3][7]+=a3*b1v.w;
        }
    }
    float* base = g_part + (size_t)ts*ROWS*DD + (size_t)(b*NN)*DD + d0;
    #pragma unroll
    for (int i = 0; i < 4; i++) {
        float* dst = base + (size_t)(n0+i)*DD + c0;
        float4 o0 = {acc[i][0], acc[i][1], acc[i][2], acc[i][3]};
        float4 o1 = {acc[i][4], acc[i][5], acc[i][6], acc[i][7]};
        *(float4*)dst = o0;
        *(float4*)(dst + 4) = o1;
    }
}

// =====================================================================
// K3b: reduce 4 partials, scale by 1/S, fused LayerNorm1 -> g_U seg 0.
// grid 2048 (one row), 256 thr
// =====================================================================
__global__ void __launch_bounds__(256) k_red_ln(const float* __restrict__ gamma,
                                               const float* __restrict__ beta)
{
    const int row = blockIdx.x;
    const int tid = threadIdx.x, lane = tid & 31, wid = tid >> 5;
    const float r = g_rs[row];
    const size_t o = (size_t)row*DD;

    float v0 = 0.0f, v1 = 0.0f;
    #pragma unroll
    for (int ts = 0; ts < 4; ts++) {
        v0 += g_part[(size_t)ts*ROWS*DD + o + tid];
        v1 += g_part[(size_t)ts*ROWS*DD + o + tid + 256];
    }
    v0 *= r; v1 *= r;

    float s = v0 + v1, sq = v0*v0 + v1*v1;
    #pragma unroll
    for (int off = 16; off > 0; off >>= 1) {
        s  += __shfl_xor_sync(0xffffffffu, s, off);
        sq += __shfl_xor_sync(0xffffffffu, sq, off);
    }
    __shared__ float ss[8], sqs[8], bc[2];
    if (lane == 0) { ss[wid] = s; sqs[wid] = sq; }
    __syncthreads();
    if (wid == 0) {
        float s2 = (lane < 8) ? ss[lane] : 0.0f;
        float q2 = (lane < 8) ? sqs[lane] : 0.0f;
        #pragma unroll
        for (int off = 4; off > 0; off >>= 1) {
            s2 += __shfl_xor_sync(0xffffffffu, s2, off);
            q2 += __shfl_xor_sync(0xffffffffu, q2, off);
        }
        if (lane == 0) {
            float mean = s2 * (1.0f/512.0f);
            float var  = q2 * (1.0f/512.0f) - mean*mean;
            bc[0] = mean;
            bc[1] = rsqrtf(var + 1e-5f);
        }
    }
    __syncthreads();
    float mean = bc[0], inv = bc[1];
    float* dst = g_U + (size_t)row*2048;
    dst[tid]       = (v0 - mean)*inv*gamma[tid]       + beta[tid];
    dst[tid + 256] = (v1 - mean)*inv*gamma[tid + 256] + beta[tid + 256];
}

// =====================================================================
// LayerNorm helper: one warp per 512-wide row
// =====================================================================
__device__ __forceinline__ void ln_row(const float* __restrict__ src,
                                       float* __restrict__ dst,
                                       const float* __restrict__ gamma,
                                       const float* __restrict__ beta,
                                       int lane)
{
    float4 v[4];
    float s = 0.0f, sq = 0.0f;
    #pragma unroll
    for (int i = 0; i < 4; i++) {
        v[i] = *(const float4*)(src + i*128 + lane*4);
        s  += v[i].x + v[i].y + v[i].z + v[i].w;
        sq += v[i].x*v[i].x + v[i].y*v[i].y + v[i].z*v[i].z + v[i].w*v[i].w;
    }
    #pragma unroll
    for (int o = 16; o > 0; o >>= 1) {
        s  += __shfl_xor_sync(0xffffffffu, s, o);
        sq += __shfl_xor_sync(0xffffffffu, sq, o);
    }
    float mean = s * (1.0f/512.0f);
    float var  = sq * (1.0f/512.0f) - mean*mean;
    float inv  = rsqrtf(var + 1e-5f);
    #pragma unroll
    for (int i = 0; i < 4; i++) {
        int c = i*128 + lane*4;
        float4 g4 = *(const float4*)(gamma + c);
        float4 b4 = *(const float4*)(beta + c);
        float4 o;
        o.x = (v[i].x - mean)*inv*g4.x + b4.x;
        o.y = (v[i].y - mean)*inv*g4.y + b4.y;
        o.z = (v[i].z - mean)*inv*g4.z + b4.z;
        o.w = (v[i].w - mean)*inv*g4.w + b4.w;
        *(float4*)(dst + c) = o;
    }
}

// =====================================================================
// K5: per-batch CQA core. grid 32, 256 thr, dyn smem 214016 B
// =====================================================================
#define QS_STRIDE 516
#define K5_SMEM ((LL*QS_STRIDE + NN*DD + 2*NN*33) * 4)
__global__ void __launch_bounds__(256) k_cqa(const float* __restrict__ query)
{
    extern __shared__ float sm[];
    float* qs = sm;                         // [32][516]  (later reused for M)
    float* fs = qs + LL*QS_STRIDE;          // [64][512]
    float* s0 = fs + NN*DD;                 // [64][33]  sim -> sim_c
    float* sr = s0 + NN*33;                 // [64][33]  sim_r

    const int b = blockIdx.x, tid = threadIdx.x;

    for (int i = tid; i < LL*128; i += 256) {
        int l = i >> 7, c4 = i & 127;
        *(float4*)(qs + l*QS_STRIDE + c4*4) =
            *(const float4*)(query + (size_t)(b*LL + l)*DD + c4*4);
    }
    for (int i = tid; i < NN*128; i += 256) {
        int n = i >> 7, c4 = i & 127;
        *(float4*)(fs + n*DD + c4*4) =
            *(const float4*)(g_U + (size_t)(b*NN + n)*2048 + c4*4);
    }
    __syncthreads();

    {
        const int l = tid & 31, ng = tid >> 5;
        #pragma unroll
        for (int j = 0; j < 8; j++) {
            int n = ng + 8*j;
            float s = 0.0f;
            #pragma unroll 4
            for (int k = 0; k < DD; k++) s += fs[n*DD + k] * qs[l*QS_STRIDE + k];
            s0[n*33 + l] = s;
        }
    }
    __syncthreads();
    if (tid < 64) {
        int n = tid;
        float M = -1e30f;
        for (int l = 0; l < 32; l++) M = fmaxf(M, s0[n*33 + l]);
        float S = 0.0f;
        for (int l = 0; l < 32; l++) S += __expf(s0[n*33 + l] - M);
        float inv = 1.0f / S;
        for (int l = 0; l < 32; l++) sr[n*33 + l] = __expf(s0[n*33 + l] - M) * inv;
    }
    __syncthreads();
    if (tid < 32) {
        int l = tid;
        float M = -1e30f;
        for (int n = 0; n < 64; n++) M = fmaxf(M, s0[n*33 + l]);
        float S = 0.0f;
        for (int n = 0; n < 64; n++) S += __expf(s0[n*33 + l] - M);
        float inv = 1.0f / S;
        for (int n = 0; n < 64; n++) s0[n*33 + l] = __expf(s0[n*33 + l] - M) * inv;
    }
    __syncthreads();

    for (int i = tid; i < NN*128; i += 256) {
        int n = i >> 7, c4 = i & 127, d = c4*4;
        float4 a = {0,0,0,0};
        #pragma unroll
        for (int l = 0; l < 32; l++) {
            float w = sr[n*33 + l];
            float4 qv = *(const float4*)(qs + l*QS_STRIDE + d);
            a.x += w*qv.x; a.y += w*qv.y; a.z += w*qv.z; a.w += w*qv.w;
        }
        float4 f = *(const float4*)(fs + n*DD + d);
        float* dst = g_U + (size_t)(b*NN + n)*2048;
        *(float4*)(dst + 512 + d) = a;
        float4 e3 = {f.x*a.x, f.y*a.y, f.z*a.z, f.w*a.w};
        *(float4*)(dst + 1024 + d) = e3;
    }
    __syncthreads();

    for (int i = tid; i < LL*128; i += 256) {
        int l = i >> 7, c4 = i & 127, d = c4*4;
        float4 m = {0,0,0,0};
        #pragma unroll 8
        for (int n = 0; n < 64; n++) {
            float w = s0[n*33 + l];
            float4 fv = *(const float4*)(fs + n*DD + d);
            m.x += w*fv.x; m.y += w*fv.y; m.z += w*fv.z; m.w += w*fv.w;
        }
        *(float4*)(qs + l*QS_STRIDE + d) = m;
    }
    __syncthreads();

    for (int i = tid; i < NN*128; i += 256) {
        int n = i >> 7, c4 = i & 127, d = c4*4;
        float4 bm = {0,0,0,0};
        #pragma unroll
        for (int l = 0; l < 32; l++) {
            float w = sr[n*33 + l];
            float4 mv = *(const float4*)(qs + l*QS_STRIDE + d);
            bm.x += w*mv.x; bm.y += w*mv.y; bm.z += w*mv.z; bm.w += w*mv.w;
        }
        float4 f = *(const float4*)(fs + n*DD + d);
        float4 e4 = {f.x*bm.x, f.y*bm.y, f.z*bm.z, f.w*bm.w};
        *(float4*)(g_U + (size_t)(b*NN + n)*2048 + 1536 + d) = e4;
    }
}

// =====================================================================
// K6: split-bf16 mma.sync  cat = U[2048,2048] @ Wf^T(+split) + bias
// grid (4 n-tiles of 128, 32 m-tiles of 64), 256 thr, static smem ~31 KB
// =====================================================================
__global__ void __launch_bounds__(256) k_headgemm_tc(
    const float* __restrict__ bf1, const float* __restrict__ bf2,
    const float* __restrict__ bf3, const float* __restrict__ bf4)
{
    __shared__ __align__(16) char Uh[64*80], Ul[64*80];     // [64 m][40 bf16]
    __shared__ __align__(16) char Wh[128*80], Wl[128*80];   // [128 n][40 bf16]
    __shared__ float bsum[128];

    const int tid = threadIdx.x;
    const int wid = tid >> 5, lane = tid & 31;
    const int wm = wid & 1, wn = wid >> 1;     // warp grid 2(M) x 4(N), warp tile 32x32
    const int n0 = blockIdx.x * 128;
    const int m0 = blockIdx.y * 64;
    if (tid < 128) bsum[tid] = bf1[n0+tid] + bf2[n0+tid] + bf3[n0+tid] + bf4[n0+tid];

    const uint32_t uhB = smem_u32(Uh), ulB = smem_u32(Ul);
    const uint32_t whB = smem_u32(Wh), wlB = smem_u32(Wl);
    const uint32_t aoff = (uint32_t)((lane & 15) * 80 + (lane >> 4) * 16);
    const uint32_t boff = (uint32_t)((lane & 7)  * 80 + ((lane >> 3) & 1) * 16);
    const int qrow = lane >> 2, qcol = (lane & 3) * 2;

    float acc[2][4][4];
    #pragma unroll
    for (int i = 0; i < 2; i++)
        #pragma unroll
        for (int j = 0; j < 4; j++)
            #pragma unroll
            for (int k = 0; k < 4; k++) acc[i][j][k] = 0.0f;

    for (int kc = 0; kc < 64; kc++) {
        __syncthreads();
        {   // U chunk [64 m][32 k] fp32 -> split
            int r = tid >> 2, seg = tid & 3;
            const float* s = g_U + (size_t)(m0 + r)*2048 + kc*32 + seg*8;
            float4 v0 = *(const float4*)s;
            float4 v1 = *(const float4*)(s + 4);
            __nv_bfloat16 h[8], l[8];
            split_bf16(v0.x, h[0], l[0]); split_bf16(v0.y, h[1], l[1]);
            split_bf16(v0.z, h[2], l[2]); split_bf16(v0.w, h[3], l[3]);
            split_bf16(v1.x, h[4], l[4]); split_bf16(v1.y, h[5], l[5]);
            split_bf16(v1.z, h[6], l[6]); split_bf16(v1.w, h[7], l[7]);
            uint4 hp = { pack_bf16(h[0],h[1]), pack_bf16(h[2],h[3]),
                         pack_bf16(h[4],h[5]), pack_bf16(h[6],h[7]) };
            uint4 lp = { pack_bf16(l[0],l[1]), pack_bf16(l[2],l[3]),
                         pack_bf16(l[4],l[5]), pack_bf16(l[6],l[7]) };
            *(uint4*)(Uh + r*80 + seg*16) = hp;
            *(uint4*)(Ul + r*80 + seg*16) = lp;
        }
        {   // W chunk [128 n][32 k] from pre-split g_wft
            int nr = tid >> 1, part = tid & 1;
            const uint4* sh = (const uint4*)(g_wft_hi + (size_t)(n0 + nr)*2048 + kc*32 + part*16);
            const uint4* sl = (const uint4*)(g_wft_lo + (size_t)(n0 + nr)*2048 + kc*32 + part*16);
            uint4 h0 = sh[0], h1 = sh[1];
            uint4 l0 = sl[0], l1 = sl[1];
            char* dh = Wh + nr*80 + part*32;
            char* dl = Wl + nr*80 + part*32;
            *(uint4*)dh = h0; *(uint4*)(dh + 16) = h1;
            *(uint4*)dl = l0; *(uint4*)(dl + 16) = l1;
        }
        __syncthreads();
        const uint32_t usrc[3] = {uhB, uhB, ulB};
        const uint32_t wsrc[3] = {whB, wlB, whB};
        #pragma unroll
        for (int p = 0; p < 3; p++) {
            uint32_t ub = usrc[p] + aoff + (uint32_t)(wm*32*80);
            uint32_t wb = wsrc[p] + boff + (uint32_t)(wn*32*80);
            #pragma unroll
            for (int ks = 0; ks < 2; ks++) {
                uint32_t a0[4], a1[4];
                ldsm_x4(a0, ub + ks*32);
                ldsm_x4(a1, ub + 16*80 + ks*32);
                #pragma unroll
                for (int nt = 0; nt < 4; nt++) {
                    uint32_t bf[2];
                    ldsm_x2(bf, wb + nt*8*80 + ks*32);
                    mma_bf16(acc[0][nt], a0, bf);
                    mma_bf16(acc[1][nt], a1, bf);
                }
            }
        }
    }

    #pragma unroll
    for (int mt = 0; mt < 2; mt++)
        #pragma unroll
        for (int nt = 0; nt < 4; nt++)
            #pragma unroll
            for (int h = 0; h < 2; h++) {
                int row = m0 + wm*32 + mt*16 + h*8 + qrow;
                int col = wn*32 + nt*8 + qcol;
                float2 v;
                v.x = acc[mt][nt][h*2+0] + bsum[col];
                v.y = acc[mt][nt][h*2+1] + bsum[col+1];
                *(float2*)(g_cat + (size_t)row*DD + n0 + col) = v;
            }
}

// K7: LN2(cat) -> d_out.  grid 256, 256 thr
__global__ void __launch_bounds__(256) k_ln2(const float* __restrict__ g,
                                             const float* __restrict__ be,
                                             float* __restrict__ out)
{
    int warp = threadIdx.x >> 5, lane = threadIdx.x & 31;
    int row = blockIdx.x * 8 + warp;
    ln_row(g_cat + (size_t)row*DD, out + (size_t)row*DD, g, be, lane);
}

// =====================================================================
extern "C" void kernel_launch(void* const* d_in, const int* in_sizes, int n_in,
                              void* d_out, int out_size)
{
    const float* input = (const float*)d_in[0];
    const float* query = (const float*)d_in[1];
    const float* w1    = (const float*)d_in[2];
    const float* b1    = (const float*)d_in[3];
    const float* w2    = (const float*)d_in[4];
    const float* b2    = (const float*)d_in[5];
    const float* ln1g  = (const float*)d_in[6];
    const float* ln1b  = (const float*)d_in[7];
    const float* wf1   = (const float*)d_in[8];
    const float* bf1   = (const float*)d_in[9];
    const float* wf2   = (const float*)d_in[10];
    const float* bf2   = (const float*)d_in[11];
    const float* wf3   = (const float*)d_in[12];
    const float* bf3   = (const float*)d_in[13];
    const float* wf4   = (const float*)d_in[14];
    const float* bf4   = (const float*)d_in[15];
    const float* ln2g  = (const float*)d_in[16];
    const float* ln2b  = (const float*)d_in[17];
    float* out = (float*)d_out;

    cudaFuncSetAttribute(k_logits_tc, cudaFuncAttributeMaxDynamicSharedMemorySize, K1TC_SMEM);
    cudaFuncSetAttribute(k_cqa,       cudaFuncAttributeMaxDynamicSharedMemorySize, K5_SMEM);

    k_tsplit<<<dim3(16,16), 256>>>(w1, 0);
    k_tsplit<<<dim3(2,16),  256>>>(w2, 1);
    k_tsplit<<<dim3(16,16), 256>>>(wf1, 2);
    k_tsplit<<<dim3(16,16), 256>>>(wf2, 3);
    k_tsplit<<<dim3(16,16), 256>>>(wf3, 4);
    k_tsplit<<<dim3(16,16), 256>>>(wf4, 5);
    k_logits_tc<<<BB*TT/128, 512, K1TC_SMEM>>>(input, b1, b2);
    k_stats<<<BB, 256>>>();
    k_feat<<<dim3(4, BB, 4), 256>>>(input);
    k_red_ln<<<ROWS, 256>>>(ln1g, ln1b);
    k_cqa<<<BB, 256, K5_SMEM>>>(query);
    k_headgemm_tc<<<dim3(4, 32), 256>>>(bf1, bf2, bf3, bf4);
    k_ln2<<<ROWS/8, 256>>>(ln2g, ln2b, out);
}

// round 10
// speedup vs baseline: 2.0612x; 1.0795x over previous
#include <cuda_runtime.h>
#include <cuda_bf16.h>
#include <cstdint>
#include <cmath>

#define BB 32
#define TT 4096
#define LL 32
#define DD 512
#define NN 64
#define ROWS (BB*NN)          // 2048

// ---------------- scratch (device globals; no allocs allowed) ----------------
__device__ float g_logits[BB*TT*NN];        // [B*T][64]   32 MB
__device__ float g_m[ROWS];
__device__ float g_rs[ROWS];
__device__ float g_part[4*ROWS*DD];         // t-split partial feat sums, 16 MB
__device__ float g_U[ROWS*2048];
__device__ float g_cat[ROWS*DD];
__device__ __nv_bfloat16 g_w1t_hi[DD*DD];   // [n=512][k=512]
__device__ __nv_bfloat16 g_w1t_lo[DD*DD];
__device__ __nv_bfloat16 g_w2t_hi[NN*DD];   // [n=64][k=512]
__device__ __nv_bfloat16 g_w2t_lo[NN*DD];
__device__ __nv_bfloat16 g_wft_hi[DD*2048]; // [n=512][k=2048]
__device__ __nv_bfloat16 g_wft_lo[DD*2048];

__device__ __forceinline__ float gelu_exact(float x) {
    return 0.5f * x * (1.0f + erff(x * 0.70710678118654752f));
}

// ===================== mma.sync / ldmatrix helpers =====================
__device__ __forceinline__ uint32_t smem_u32(const void* p) {
    uint32_t a;
    asm("{ .reg .u64 t; cvta.to.shared.u64 t, %1; cvt.u32.u64 %0, t; }" : "=r"(a) : "l"(p));
    return a;
}
__device__ __forceinline__ void ldsm_x4(uint32_t r[4], uint32_t addr) {
    asm volatile("ldmatrix.sync.aligned.m8n8.x4.shared.b16 {%0,%1,%2,%3}, [%4];"
        : "=r"(r[0]), "=r"(r[1]), "=r"(r[2]), "=r"(r[3]) : "r"(addr));
}
__device__ __forceinline__ void ldsm_x2(uint32_t r[2], uint32_t addr) {
    asm volatile("ldmatrix.sync.aligned.m8n8.x2.shared.b16 {%0,%1}, [%2];"
        : "=r"(r[0]), "=r"(r[1]) : "r"(addr));
}
__device__ __forceinline__ void ldsm_x2t(uint32_t r[2], uint32_t addr) {
    asm volatile("ldmatrix.sync.aligned.m8n8.x2.trans.shared.b16 {%0,%1}, [%2];"
        : "=r"(r[0]), "=r"(r[1]) : "r"(addr));
}
__device__ __forceinline__ void mma_bf16(float* d, const uint32_t* a, const uint32_t* b) {
    asm volatile("mma.sync.aligned.m16n8k16.row.col.f32.bf16.bf16.f32 "
        "{%0,%1,%2,%3}, {%4,%5,%6,%7}, {%8,%9}, {%0,%1,%2,%3};"
        : "+f"(d[0]), "+f"(d[1]), "+f"(d[2]), "+f"(d[3])
        : "r"(a[0]), "r"(a[1]), "r"(a[2]), "r"(a[3]), "r"(b[0]), "r"(b[1]));
}
__device__ __forceinline__ uint32_t pack_bf16(__nv_bfloat16 a, __nv_bfloat16 b) {
    return ((uint32_t)__bfloat16_as_ushort(b) << 16) | (uint32_t)__bfloat16_as_ushort(a);
}
__device__ __forceinline__ void split_bf16(float x, __nv_bfloat16& h, __nv_bfloat16& l) {
    h = __float2bfloat16(x);
    l = __float2bfloat16(x - __bfloat162float(h));
}

// =====================================================================
// K0: coalesced transpose + split (unchanged)
// =====================================================================
__global__ void __launch_bounds__(256) k_tsplit(const float* __restrict__ src, int sel)
{
    __shared__ float tile[32][33];
    int ncols, dstride, doff;
    __nv_bfloat16 *dh, *dl;
    if (sel == 0)      { ncols = 512; dstride = 512;  doff = 0; dh = g_w1t_hi; dl = g_w1t_lo; }
    else if (sel == 1) { ncols = 64;  dstride = 512;  doff = 0; dh = g_w2t_hi; dl = g_w2t_lo; }
    else               { ncols = 512; dstride = 2048; doff = (sel-2)*512; dh = g_wft_hi; dl = g_wft_lo; }

    const int n0 = blockIdx.x * 32, k0 = blockIdx.y * 32;
    const int tx = threadIdx.x & 31, ty = threadIdx.x >> 5;
    #pragma unroll
    for (int i = 0; i < 4; i++) {
        int r = ty + i*8;
        tile[r][tx] = src[(size_t)(k0 + r)*ncols + n0 + tx];
    }
    __syncthreads();
    #pragma unroll
    for (int i = 0; i < 4; i++) {
        int r = ty + i*8;
        float x = tile[tx][r];
        __nv_bfloat16 h, l; split_bf16(x, h, l);
        size_t o = (size_t)(n0 + r)*dstride + doff + k0 + tx;
        dh[o] = h; dl[o] = l;
    }
}

// =====================================================================
// K1: split-bf16 mma.sync  logits = GELU(X@w1+b1)@w2 + b2
// Double-buffered GEMM1 (1 sync/chunk), per-half H staging.
// grid 1024, 512 thr, dyn smem 194816 B
// =====================================================================
#define SM1_XH0   0
#define SM1_XH1   10240
#define SM1_XL0   20480
#define SM1_XL1   30720
#define SM1_W1H0  40960
#define SM1_W1H1  61440
#define SM1_W1L0  81920
#define SM1_W1L1  102400
#define SM1_HHI   122880     // [128][272B] = 34816
#define SM1_HLO   157696
#define SM1_W2H   0          // reuses X region during GEMM2
#define SM1_W2L   5120
#define SM1_B1    192512
#define SM1_B2    194560
#define K1TC_SMEM 194816

__global__ void __launch_bounds__(512, 1) k_logits_tc(
    const float* __restrict__ input,
    const float* __restrict__ b1, const float* __restrict__ b2)
{
    extern __shared__ char smem[];
    const uint32_t sb = smem_u32(smem);
    const int tid = threadIdx.x;
    const int wid = tid >> 5, lane = tid & 31;
    const int wm = wid & 3, wn = wid >> 2;       // 4(M) x 4(N)
    const size_t t0 = (size_t)blockIdx.x * 128;

    float* b1s = (float*)(smem + SM1_B1);
    float* b2s = (float*)(smem + SM1_B2);
    b1s[tid & 511] = b1[tid & 511];
    if (tid < 64) b2s[tid] = b2[tid];

    const uint32_t aoffX = (uint32_t)((lane & 15) * 80  + (lane >> 4) * 16);
    const uint32_t boffW = (uint32_t)((lane & 7)  * 80  + ((lane >> 3) & 1) * 16);
    const uint32_t aoffH = (uint32_t)((lane & 15) * 272 + (lane >> 4) * 16);
    const uint32_t boff2 = (uint32_t)((lane & 7)  * 80  + ((lane >> 3) & 1) * 16);
    const int qrow = lane >> 2, qcol = (lane & 3) * 2;

    const int xrow = tid >> 2, xseg = tid & 3;
    const int w1n  = tid >> 1, w1p  = tid & 1;
    const int w2n  = tid >> 3, w2s  = tid & 7;

    float acc2[2][2][4];
    #pragma unroll
    for (int i = 0; i < 2; i++)
        #pragma unroll
        for (int j = 0; j < 2; j++)
            #pragma unroll
            for (int k = 0; k < 4; k++) acc2[i][j][k] = 0.0f;

    for (int nc = 0; nc < 2; nc++) {
        float acc[2][8][4];
        #pragma unroll
        for (int i = 0; i < 2; i++)
            #pragma unroll
            for (int j = 0; j < 8; j++)
                #pragma unroll
                for (int k = 0; k < 4; k++) acc[i][j][k] = 0.0f;

        float4 xr0, xr1;
        uint4 w1r[4];
        {
            const float* s = input + (t0 + xrow)*DD + xseg*8;
            xr0 = *(const float4*)s; xr1 = *(const float4*)(s + 4);
            const uint4* sh = (const uint4*)(g_w1t_hi + (size_t)(nc*256 + w1n)*512 + w1p*16);
            const uint4* sl = (const uint4*)(g_w1t_lo + (size_t)(nc*256 + w1n)*512 + w1p*16);
            w1r[0] = sh[0]; w1r[1] = sh[1]; w1r[2] = sl[0]; w1r[3] = sl[1];
        }

        for (int kc = 0; kc < 16; kc++) {
            const uint32_t bufX  = (kc & 1) ? SM1_XH1  : SM1_XH0;
            const uint32_t bufXL = (kc & 1) ? SM1_XL1  : SM1_XL0;
            const uint32_t bufW  = (kc & 1) ? SM1_W1H1 : SM1_W1H0;
            const uint32_t bufWL = (kc & 1) ? SM1_W1L1 : SM1_W1L0;
            {
                __nv_bfloat16 h[8], l[8];
                split_bf16(xr0.x, h[0], l[0]); split_bf16(xr0.y, h[1], l[1]);
                split_bf16(xr0.z, h[2], l[2]); split_bf16(xr0.w, h[3], l[3]);
                split_bf16(xr1.x, h[4], l[4]); split_bf16(xr1.y, h[5], l[5]);
                split_bf16(xr1.z, h[6], l[6]); split_bf16(xr1.w, h[7], l[7]);
                uint4 hp = { pack_bf16(h[0],h[1]), pack_bf16(h[2],h[3]),
                             pack_bf16(h[4],h[5]), pack_bf16(h[6],h[7]) };
                uint4 lp = { pack_bf16(l[0],l[1]), pack_bf16(l[2],l[3]),
                             pack_bf16(l[4],l[5]), pack_bf16(l[6],l[7]) };
                *(uint4*)(smem + bufX  + xrow*80 + xseg*16) = hp;
                *(uint4*)(smem + bufXL + xrow*80 + xseg*16) = lp;
                char* dh = smem + bufW  + w1n*80 + w1p*32;
                char* dl = smem + bufWL + w1n*80 + w1p*32;
                *(uint4*)dh = w1r[0]; *(uint4*)(dh + 16) = w1r[1];
                *(uint4*)dl = w1r[2]; *(uint4*)(dl + 16) = w1r[3];
            }
            if (kc < 15) {
                const float* s = input + (t0 + xrow)*DD + (kc+1)*32 + xseg*8;
                xr0 = *(const float4*)s; xr1 = *(const float4*)(s + 4);
                const uint4* sh = (const uint4*)(g_w1t_hi + (size_t)(nc*256 + w1n)*512 + (kc+1)*32 + w1p*16);
                const uint4* sl = (const uint4*)(g_w1t_lo + (size_t)(nc*256 + w1n)*512 + (kc+1)*32 + w1p*16);
                w1r[0] = sh[0]; w1r[1] = sh[1]; w1r[2] = sl[0]; w1r[3] = sl[1];
            }
            __syncthreads();
            const uint32_t xsrc[3] = {bufX, bufX, bufXL};
            const uint32_t wsrc[3] = {bufW, bufWL, bufW};
            #pragma unroll
            for (int p = 0; p < 3; p++) {
                uint32_t xb = sb + xsrc[p] + aoffX + (uint32_t)(wm*32*80);
                uint32_t wb = sb + wsrc[p] + boffW + (uint32_t)(wn*64*80);
                #pragma unroll
                for (int ks = 0; ks < 2; ks++) {
                    uint32_t a0[4], a1[4];
                    ldsm_x4(a0, xb + ks*32);
                    ldsm_x4(a1, xb + 16*80 + ks*32);
                    #pragma unroll
                    for (int nt = 0; nt < 8; nt++) {
                        uint32_t bf[2];
                        ldsm_x2(bf, wb + nt*8*80 + ks*32);
                        mma_bf16(acc[0][nt], a0, bf);
                        mma_bf16(acc[1][nt], a1, bf);
                    }
                }
            }
        }

        for (int h = 0; h < 2; h++) {
            if (h) __syncthreads();
            if ((wn >> 1) == h) {
                #pragma unroll
                for (int mt = 0; mt < 2; mt++)
                    #pragma unroll
                    for (int nt = 0; nt < 8; nt++)
                        #pragma unroll
                        for (int hh = 0; hh < 2; hh++) {
                            int row = wm*32 + mt*16 + hh*8 + qrow;
                            int col = wn*64 + nt*8 + qcol;
                            float x0 = acc[mt][nt][hh*2+0] + b1s[nc*256 + col];
                            float x1 = acc[mt][nt][hh*2+1] + b1s[nc*256 + col + 1];
                            float g0 = gelu_exact(x0), g1 = gelu_exact(x1);
                            __nv_bfloat16 hh0, ll0, hh1, ll1;
                            split_bf16(g0, hh0, ll0); split_bf16(g1, hh1, ll1);
                            int c = col & 127;
                            *(uint32_t*)(smem + SM1_HHI + row*272 + c*2) = pack_bf16(hh0, hh1);
                            *(uint32_t*)(smem + SM1_HLO + row*272 + c*2) = pack_bf16(ll0, ll1);
                        }
            }
            __syncthreads();

            for (int kc2 = 0; kc2 < 4; kc2++) {
                if (kc2 > 0) __syncthreads();
                {
                    const int koff = w2s * 4;
                    *(uint2*)(smem + SM1_W2H + w2n*80 + w2s*8) =
                        *(const uint2*)(g_w2t_hi + (size_t)w2n*512 + nc*256 + h*128 + kc2*32 + koff);
                    *(uint2*)(smem + SM1_W2L + w2n*80 + w2s*8) =
                        *(const uint2*)(g_w2t_lo + (size_t)w2n*512 + nc*256 + h*128 + kc2*32 + koff);
                }
                __syncthreads();
                const uint32_t hsrc[3]  = {SM1_HHI, SM1_HHI, SM1_HLO};
                const uint32_t w2src[3] = {SM1_W2H, SM1_W2L, SM1_W2H};
                #pragma unroll
                for (int p = 0; p < 3; p++) {
                    uint32_t hb  = sb + hsrc[p]  + aoffH + (uint32_t)(wm*32*272) + (uint32_t)(kc2*64);
                    uint32_t w2b = sb + w2src[p] + boff2 + (uint32_t)(wn*16*80);
                    #pragma unroll
                    for (int ks = 0; ks < 2; ks++) {
                        uint32_t a0[4], a1[4];
                        ldsm_x4(a0, hb + ks*32);
                        ldsm_x4(a1, hb + 16*272 + ks*32);
                        #pragma unroll
                        for (int nt = 0; nt < 2; nt++) {
                            uint32_t bf[2];
                            ldsm_x2(bf, w2b + nt*8*80 + ks*32);
                            mma_bf16(acc2[0][nt], a0, bf);
                            mma_bf16(acc2[1][nt], a1, bf);
                        }
                    }
                }
            }
            __syncthreads();
        }
    }

    #pragma unroll
    for (int mt = 0; mt < 2; mt++)
        #pragma unroll
        for (int nt = 0; nt < 2; nt++)
            #pragma unroll
            for (int h = 0; h < 2; h++) {
                int row = wm*32 + mt*16 + h*8 + qrow;
                int col = wn*16 + nt*8 + qcol;
                float2 v;
                v.x = acc2[mt][nt][h*2+0] + b2s[col];
                v.y = acc2[mt][nt][h*2+1] + b2s[col+1];
                *(float2*)(g_logits + (t0 + row)*NN + col) = v;
            }
}

// =====================================================================
// K2: per-(b,n) online max & sumexp over T   (grid 32, 256 thr)
// =====================================================================
__global__ void __launch_bounds__(256) k_stats()
{
    const int b = blockIdx.x, tid = threadIdx.x;
    const int n = tid & 63, tg = tid >> 6;
    const float* base = g_logits + (size_t)b*TT*NN;
    float m = -1e30f, s = 0.0f;
    for (int t = tg; t < TT; t += 4) {
        float v = base[(size_t)t*NN + n];
        if (v <= m) s += __expf(v - m);
        else { s = s * __expf(m - v) + 1.0f; m = v; }
    }
    __shared__ float sm_m[4][64], sm_s[4][64];
    sm_m[tg][n] = m; sm_s[tg][n] = s;
    __syncthreads();
    if (tid < 64) {
        float M = sm_m[0][tid];
        #pragma unroll
        for (int i = 1; i < 4; i++) M = fmaxf(M, sm_m[i][tid]);
        float S = 0.0f;
        #pragma unroll
        for (int i = 0; i < 4; i++) S += sm_s[i][tid] * __expf(sm_m[i][tid] - M);
        g_m[b*NN + tid] = M;
        g_rs[b*NN + tid] = 1.0f / S;
    }
}

// =====================================================================
// K3: feat partials via split-bf16 mma.sync.
// grid (4 d-tiles, 32 b, 4 t-slabs), 256 thr (8 warps: 2M x 4N)
// A = P^T [64 n][32 t]  (written transposed, normal ldsm, pitch 80)
// B = X   [32 t][128 d] (ldmatrix.x2.trans, pitch 272)
// =====================================================================
#define FT_PP 80      // P^T row pitch (bytes) — MUST be multiple of 16 for ldmatrix
#define FT_XP 272     // X row pitch (bytes)
__global__ void __launch_bounds__(256, 2) k_feat_tc(const float* __restrict__ input)
{
    __shared__ __align__(16) char PH[64*FT_PP], PL[64*FT_PP];   // 5120 B each
    __shared__ __align__(16) char XH[32*FT_XP], XL[32*FT_XP];   // 8704 B each
    __shared__ float ms[64];

    const int b = blockIdx.y;
    const int d0 = blockIdx.x * 128;
    const int ts = blockIdx.z;
    const int tid = threadIdx.x;
    const int wid = tid >> 5, lane = tid & 31;
    const int wm = wid & 1, wn = wid >> 1;     // 2(M=n) x 4(N=d), warp tile 32x32
    if (tid < 64) ms[tid] = g_m[b*NN + tid];

    const uint32_t phB = smem_u32(PH), plB = smem_u32(PL);
    const uint32_t xhB = smem_u32(XH), xlB = smem_u32(XL);
    const uint32_t aoff = (uint32_t)((lane & 15) * FT_PP + (lane >> 4) * 16);
    const uint32_t boffT = (uint32_t)((lane & 15) * FT_XP);    // trans: lane -> t row
    const int qrow = lane >> 2, qcol = (lane & 3) * 2;

    const int pt = tid >> 3, pn8 = (tid & 7) * 8;   // P: one t, 8 n
    const int xt = tid >> 3, xds = (tid & 7) * 16;  // X: one t, 16 d

    float acc[2][4][4];
    #pragma unroll
    for (int i = 0; i < 2; i++)
        #pragma unroll
        for (int j = 0; j < 4; j++)
            #pragma unroll
            for (int k = 0; k < 4; k++) acc[i][j][k] = 0.0f;

    const float* L = g_logits + (size_t)b*TT*NN;
    const float* X = input + (size_t)b*TT*DD;

    for (int kt = 0; kt < 32; kt++) {
        const int t0 = (ts*32 + kt) * 32;
        __syncthreads();
        {   // P^T: 8 exps, store transposed [n][t] hi/lo
            float4 v0 = *(const float4*)(L + (size_t)(t0+pt)*NN + pn8);
            float4 v1 = *(const float4*)(L + (size_t)(t0+pt)*NN + pn8 + 4);
            float e[8];
            e[0]=__expf(v0.x - ms[pn8+0]); e[1]=__expf(v0.y - ms[pn8+1]);
            e[2]=__expf(v0.z - ms[pn8+2]); e[3]=__expf(v0.w - ms[pn8+3]);
            e[4]=__expf(v1.x - ms[pn8+4]); e[5]=__expf(v1.y - ms[pn8+5]);
            e[6]=__expf(v1.z - ms[pn8+6]); e[7]=__expf(v1.w - ms[pn8+7]);
            #pragma unroll
            for (int j = 0; j < 8; j++) {
                __nv_bfloat16 h, l; split_bf16(e[j], h, l);
                *(uint16_t*)(PH + (pn8+j)*FT_PP + pt*2) = __bfloat16_as_ushort(h);
                *(uint16_t*)(PL + (pn8+j)*FT_PP + pt*2) = __bfloat16_as_ushort(l);
            }
        }
        {   // X tile [32 t][128 d] fp32 -> bf16 hi/lo rows
            const float* s = X + (size_t)(t0+xt)*DD + d0 + xds;
            float4 v0 = *(const float4*)s,      v1 = *(const float4*)(s+4);
            float4 v2 = *(const float4*)(s+8),  v3 = *(const float4*)(s+12);
            __nv_bfloat16 h[16], l[16];
            split_bf16(v0.x,h[0],l[0]);  split_bf16(v0.y,h[1],l[1]);
            split_bf16(v0.z,h[2],l[2]);  split_bf16(v0.w,h[3],l[3]);
            split_bf16(v1.x,h[4],l[4]);  split_bf16(v1.y,h[5],l[5]);
            split_bf16(v1.z,h[6],l[6]);  split_bf16(v1.w,h[7],l[7]);
            split_bf16(v2.x,h[8],l[8]);  split_bf16(v2.y,h[9],l[9]);
            split_bf16(v2.z,h[10],l[10]); split_bf16(v2.w,h[11],l[11]);
            split_bf16(v3.x,h[12],l[12]); split_bf16(v3.y,h[13],l[13]);
            split_bf16(v3.z,h[14],l[14]); split_bf16(v3.w,h[15],l[15]);
            uint4 hp0 = { pack_bf16(h[0],h[1]), pack_bf16(h[2],h[3]),
                          pack_bf16(h[4],h[5]), pack_bf16(h[6],h[7]) };
            uint4 hp1 = { pack_bf16(h[8],h[9]), pack_bf16(h[10],h[11]),
                          pack_bf16(h[12],h[13]), pack_bf16(h[14],h[15]) };
            uint4 lp0 = { pack_bf16(l[0],l[1]), pack_bf16(l[2],l[3]),
                          pack_bf16(l[4],l[5]), pack_bf16(l[6],l[7]) };
            uint4 lp1 = { pack_bf16(l[8],l[9]), pack_bf16(l[10],l[11]),
                          pack_bf16(l[12],l[13]), pack_bf16(l[14],l[15]) };
            char* dh = XH + xt*FT_XP + xds*2;
            char* dl = XL + xt*FT_XP + xds*2;
            *(uint4*)dh = hp0; *(uint4*)(dh+16) = hp1;
            *(uint4*)dl = lp0; *(uint4*)(dl+16) = lp1;
        }
        __syncthreads();
        const uint32_t asrc[3] = {phB, phB, plB};
        const uint32_t bsrc[3] = {xhB, xlB, xhB};
        #pragma unroll
        for (int p = 0; p < 3; p++) {
            uint32_t ab = asrc[p] + aoff + (uint32_t)(wm*32*FT_PP);
            uint32_t bb = bsrc[p] + boffT + (uint32_t)((wn*32)*2);
            #pragma unroll
            for (int ks = 0; ks < 2; ks++) {
                uint32_t a0[4], a1[4];
                ldsm_x4(a0, ab + ks*32);
                ldsm_x4(a1, ab + 16*FT_PP + ks*32);
                #pragma unroll
                for (int nt = 0; nt < 4; nt++) {
                    uint32_t bf[2];
                    ldsm_x2t(bf, bb + (uint32_t)(ks*16*FT_XP) + (uint32_t)(nt*16));
                    mma_bf16(acc[0][nt], a0, bf);
                    mma_bf16(acc[1][nt], a1, bf);
                }
            }
        }
    }

    float* base = g_part + (size_t)ts*ROWS*DD + (size_t)(b*NN)*DD + d0;
    #pragma unroll
    for (int mt = 0; mt < 2; mt++)
        #pragma unroll
        for (int nt = 0; nt < 4; nt++)
            #pragma unroll
            for (int h = 0; h < 2; h++) {
                int n = wm*32 + mt*16 + h*8 + qrow;
                int d = wn*32 + nt*8 + qcol;
                float2 v = { acc[mt][nt][h*2+0], acc[mt][nt][h*2+1] };
                *(float2*)(base + (size_t)n*DD + d) = v;
            }
}

// =====================================================================
// K3b: reduce 4 partials, scale by 1/S, fused LayerNorm1 -> g_U seg 0.
// =====================================================================
__global__ void __launch_bounds__(256) k_red_ln(const float* __restrict__ gamma,
                                               const float* __restrict__ beta)
{
    const int row = blockIdx.x;
    const int tid = threadIdx.x, lane = tid & 31, wid = tid >> 5;
    const float r = g_rs[row];
    const size_t o = (size_t)row*DD;

    float v0 = 0.0f, v1 = 0.0f;
    #pragma unroll
    for (int ts = 0; ts < 4; ts++) {
        v0 += g_part[(size_t)ts*ROWS*DD + o + tid];
        v1 += g_part[(size_t)ts*ROWS*DD + o + tid + 256];
    }
    v0 *= r; v1 *= r;

    float s = v0 + v1, sq = v0*v0 + v1*v1;
    #pragma unroll
    for (int off = 16; off > 0; off >>= 1) {
        s  += __shfl_xor_sync(0xffffffffu, s, off);
        sq += __shfl_xor_sync(0xffffffffu, sq, off);
    }
    __shared__ float ss[8], sqs[8], bc[2];
    if (lane == 0) { ss[wid] = s; sqs[wid] = sq; }
    __syncthreads();
    if (wid == 0) {
        float s2 = (lane < 8) ? ss[lane] : 0.0f;
        float q2 = (lane < 8) ? sqs[lane] : 0.0f;
        #pragma unroll
        for (int off = 4; off > 0; off >>= 1) {
            s2 += __shfl_xor_sync(0xffffffffu, s2, off);
            q2 += __shfl_xor_sync(0xffffffffu, q2, off);
        }
        if (lane == 0) {
            float mean = s2 * (1.0f/512.0f);
            float var  = q2 * (1.0f/512.0f) - mean*mean;
            bc[0] = mean;
            bc[1] = rsqrtf(var + 1e-5f);
        }
    }
    __syncthreads();
    float mean = bc[0], inv = bc[1];
    float* dst = g_U + (size_t)row*2048;
    dst[tid]       = (v0 - mean)*inv*gamma[tid]       + beta[tid];
    dst[tid + 256] = (v1 - mean)*inv*gamma[tid + 256] + beta[tid + 256];
}

// =====================================================================
// LayerNorm helper: one warp per 512-wide row
// =====================================================================
__device__ __forceinline__ void ln_row(const float* __restrict__ src,
                                       float* __restrict__ dst,
                                       const float* __restrict__ gamma,
                                       const float* __restrict__ beta,
                                       int lane)
{
    float4 v[4];
    float s = 0.0f, sq = 0.0f;
    #pragma unroll
    for (int i = 0; i < 4; i++) {
        v[i] = *(const float4*)(src + i*128 + lane*4);
        s  += v[i].x + v[i].y + v[i].z + v[i].w;
        sq += v[i].x*v[i].x + v[i].y*v[i].y + v[i].z*v[i].z + v[i].w*v[i].w;
    }
    #pragma unroll
    for (int o = 16; o > 0; o >>= 1) {
        s  += __shfl_xor_sync(0xffffffffu, s, o);
        sq += __shfl_xor_sync(0xffffffffu, sq, o);
    }
    float mean = s * (1.0f/512.0f);
    float var  = sq * (1.0f/512.0f) - mean*mean;
    float inv  = rsqrtf(var + 1e-5f);
    #pragma unroll
    for (int i = 0; i < 4; i++) {
        int c = i*128 + lane*4;
        float4 g4 = *(const float4*)(gamma + c);
        float4 b4 = *(const float4*)(beta + c);
        float4 o;
        o.x = (v[i].x - mean)*inv*g4.x + b4.x;
        o.y = (v[i].y - mean)*inv*g4.y + b4.y;
        o.z = (v[i].z - mean)*inv*g4.z + b4.z;
        o.w = (v[i].w - mean)*inv*g4.w + b4.w;
        *(float4*)(dst + c) = o;
    }
}

// =====================================================================
// K5: per-batch CQA core. grid 32, 256 thr, dyn smem 214016 B
// =====================================================================
#define QS_STRIDE 516
#define K5_SMEM ((LL*QS_STRIDE + NN*DD + 2*NN*33) * 4)
__global__ void __launch_bounds__(256) k_cqa(const float* __restrict__ query)
{
    extern __shared__ float sm[];
    float* qs = sm;
    float* fs = qs + LL*QS_STRIDE;
    float* s0 = fs + NN*DD;
    float* sr = s0 + NN*33;

    const int b = blockIdx.x, tid = threadIdx.x;

    for (int i = tid; i < LL*128; i += 256) {
        int l = i >> 7, c4 = i & 127;
        *(float4*)(qs + l*QS_STRIDE + c4*4) =
            *(const float4*)(query + (size_t)(b*LL + l)*DD + c4*4);
    }
    for (int i = tid; i < NN*128; i += 256) {
        int n = i >> 7, c4 = i & 127;
        *(float4*)(fs + n*DD + c4*4) =
            *(const float4*)(g_U + (size_t)(b*NN + n)*2048 + c4*4);
    }
    __syncthreads();

    {
        const int l = tid & 31, ng = tid >> 5;
        #pragma unroll
        for (int j = 0; j < 8; j++) {
            int n = ng + 8*j;
            float s = 0.0f;
            #pragma unroll 4
            for (int k = 0; k < DD; k++) s += fs[n*DD + k] * qs[l*QS_STRIDE + k];
            s0[n*33 + l] = s;
        }
    }
    __syncthreads();
    if (tid < 64) {
        int n = tid;
        float M = -1e30f;
        for (int l = 0; l < 32; l++) M = fmaxf(M, s0[n*33 + l]);
        float S = 0.0f;
        for (int l = 0; l < 32; l++) S += __expf(s0[n*33 + l] - M);
        float inv = 1.0f / S;
        for (int l = 0; l < 32; l++) sr[n*33 + l] = __expf(s0[n*33 + l] - M) * inv;
    }
    __syncthreads();
    if (tid < 32) {
        int l = tid;
        float M = -1e30f;
        for (int n = 0; n < 64; n++) M = fmaxf(M, s0[n*33 + l]);
        float S = 0.0f;
        for (int n = 0; n < 64; n++) S += __expf(s0[n*33 + l] - M);
        float inv = 1.0f / S;
        for (int n = 0; n < 64; n++) s0[n*33 + l] = __expf(s0[n*33 + l] - M) * inv;
    }
    __syncthreads();

    for (int i = tid; i < NN*128; i += 256) {
        int n = i >> 7, c4 = i & 127, d = c4*4;
        float4 a = {0,0,0,0};
        #pragma unroll
        for (int l = 0; l < 32; l++) {
            float w = sr[n*33 + l];
            float4 qv = *(const float4*)(qs + l*QS_STRIDE + d);
            a.x += w*qv.x; a.y += w*qv.y; a.z += w*qv.z; a.w += w*qv.w;
        }
        float4 f = *(const float4*)(fs + n*DD + d);
        float* dst = g_U + (size_t)(b*NN + n)*2048;
        *(float4*)(dst + 512 + d) = a;
        float4 e3 = {f.x*a.x, f.y*a.y, f.z*a.z, f.w*a.w};
        *(float4*)(dst + 1024 + d) = e3;
    }
    __syncthreads();

    for (int i = tid; i < LL*128; i += 256) {
        int l = i >> 7, c4 = i & 127, d = c4*4;
        float4 m = {0,0,0,0};
        #pragma unroll 8
        for (int n = 0; n < 64; n++) {
            float w = s0[n*33 + l];
            float4 fv = *(const float4*)(fs + n*DD + d);
            m.x += w*fv.x; m.y += w*fv.y; m.z += w*fv.z; m.w += w*fv.w;
        }
        *(float4*)(qs + l*QS_STRIDE + d) = m;
    }
    __syncthreads();

    for (int i = tid; i < NN*128; i += 256) {
        int n = i >> 7, c4 = i & 127, d = c4*4;
        float4 bm = {0,0,0,0};
        #pragma unroll
        for (int l = 0; l < 32; l++) {
            float w = sr[n*33 + l];
            float4 mv = *(const float4*)(qs + l*QS_STRIDE + d);
            bm.x += w*mv.x; bm.y += w*mv.y; bm.z += w*mv.z; bm.w += w*mv.w;
        }
        float4 f = *(const float4*)(fs + n*DD + d);
        float4 e4 = {f.x*bm.x, f.y*bm.y, f.z*bm.z, f.w*bm.w};
        *(float4*)(g_U + (size_t)(b*NN + n)*2048 + 1536 + d) = e4;
    }
}

// =====================================================================
// K6: split-bf16 mma.sync  cat = U @ Wf^T + bias  (unchanged)
// =====================================================================
__global__ void __launch_bounds__(256) k_headgemm_tc(
    const float* __restrict__ bf1, const float* __restrict__ bf2,
    const float* __restrict__ bf3, const float* __restrict__ bf4)
{
    __shared__ __align__(16) char Uh[64*80], Ul[64*80];
    __shared__ __align__(16) char Wh[128*80], Wl[128*80];
    __shared__ float bsum[128];

    const int tid = threadIdx.x;
    const int wid = tid >> 5, lane = tid & 31;
    const int wm = wid & 1, wn = wid >> 1;
    const int n0 = blockIdx.x * 128;
    const int m0 = blockIdx.y * 64;
    if (tid < 128) bsum[tid] = bf1[n0+tid] + bf2[n0+tid] + bf3[n0+tid] + bf4[n0+tid];

    const uint32_t uhB = smem_u32(Uh), ulB = smem_u32(Ul);
    const uint32_t whB = smem_u32(Wh), wlB = smem_u32(Wl);
    const uint32_t aoff = (uint32_t)((lane & 15) * 80 + (lane >> 4) * 16);
    const uint32_t boff = (uint32_t)((lane & 7)  * 80 + ((lane >> 3) & 1) * 16);
    const int qrow = lane >> 2, qcol = (lane & 3) * 2;

    float acc[2][4][4];
    #pragma unroll
    for (int i = 0; i < 2; i++)
        #pragma unroll
        for (int j = 0; j < 4; j++)
            #pragma unroll
            for (int k = 0; k < 4; k++) acc[i][j][k] = 0.0f;

    for (int kc = 0; kc < 64; kc++) {
        __syncthreads();
        {
            int r = tid >> 2, seg = tid & 3;
            const float* s = g_U + (size_t)(m0 + r)*2048 + kc*32 + seg*8;
            float4 v0 = *(const float4*)s;
            float4 v1 = *(const float4*)(s + 4);
            __nv_bfloat16 h[8], l[8];
            split_bf16(v0.x, h[0], l[0]); split_bf16(v0.y, h[1], l[1]);
            split_bf16(v0.z, h[2], l[2]); split_bf16(v0.w, h[3], l[3]);
            split_bf16(v1.x, h[4], l[4]); split_bf16(v1.y, h[5], l[5]);
            split_bf16(v1.z, h[6], l[6]); split_bf16(v1.w, h[7], l[7]);
            uint4 hp = { pack_bf16(h[0],h[1]), pack_bf16(h[2],h[3]),
                         pack_bf16(h[4],h[5]), pack_bf16(h[6],h[7]) };
            uint4 lp = { pack_bf16(l[0],l[1]), pack_bf16(l[2],l[3]),
                         pack_bf16(l[4],l[5]), pack_bf16(l[6],l[7]) };
            *(uint4*)(Uh + r*80 + seg*16) = hp;
            *(uint4*)(Ul + r*80 + seg*16) = lp;
        }
        {
            int nr = tid >> 1, part = tid & 1;
            const uint4* sh = (const uint4*)(g_wft_hi + (size_t)(n0 + nr)*2048 + kc*32 + part*16);
            const uint4* sl = (const uint4*)(g_wft_lo + (size_t)(n0 + nr)*2048 + kc*32 + part*16);
            uint4 h0 = sh[0], h1 = sh[1];
            uint4 l0 = sl[0], l1 = sl[1];
            char* dh = Wh + nr*80 + part*32;
            char* dl = Wl + nr*80 + part*32;
            *(uint4*)dh = h0; *(uint4*)(dh + 16) = h1;
            *(uint4*)dl = l0; *(uint4*)(dl + 16) = l1;
        }
        __syncthreads();
        const uint32_t usrc[3] = {uhB, uhB, ulB};
        const uint32_t wsrc[3] = {whB, wlB, whB};
        #pragma unroll
        for (int p = 0; p < 3; p++) {
            uint32_t ub = usrc[p] + aoff + (uint32_t)(wm*32*80);
            uint32_t wb = wsrc[p] + boff + (uint32_t)(wn*32*80);
            #pragma unroll
            for (int ks = 0; ks < 2; ks++) {
                uint32_t a0[4], a1[4];
                ldsm_x4(a0, ub + ks*32);
                ldsm_x4(a1, ub + 16*80 + ks*32);
                #pragma unroll
                for (int nt = 0; nt < 4; nt++) {
                    uint32_t bf[2];
                    ldsm_x2(bf, wb + nt*8*80 + ks*32);
                    mma_bf16(acc[0][nt], a0, bf);
                    mma_bf16(acc[1][nt], a1, bf);
                }
            }
        }
    }

    #pragma unroll
    for (int mt = 0; mt < 2; mt++)
        #pragma unroll
        for (int nt = 0; nt < 4; nt++)
            #pragma unroll
            for (int h = 0; h < 2; h++) {
                int row = m0 + wm*32 + mt*16 + h*8 + qrow;
                int col = wn*32 + nt*8 + qcol;
                float2 v;
                v.x = acc[mt][nt][h*2+0] + bsum[col];
                v.y = acc[mt][nt][h*2+1] + bsum[col+1];
                *(float2*)(g_cat + (size_t)row*DD + n0 + col) = v;
            }
}

// K7: LN2(cat) -> d_out.  grid 256, 256 thr
__global__ void __launch_bounds__(256) k_ln2(const float* __restrict__ g,
                                             const float* __restrict__ be,
                                             float* __restrict__ out)
{
    int warp = threadIdx.x >> 5, lane = threadIdx.x & 31;
    int row = blockIdx.x * 8 + warp;
    ln_row(g_cat + (size_t)row*DD, out + (size_t)row*DD, g, be, lane);
}

// =====================================================================
extern "C" void kernel_launch(void* const* d_in, const int* in_sizes, int n_in,
                              void* d_out, int out_size)
{
    const float* input = (const float*)d_in[0];
    const float* query = (const float*)d_in[1];
    const float* w1    = (const float*)d_in[2];
    const float* b1    = (const float*)d_in[3];
    const float* w2    = (const float*)d_in[4];
    const float* b2    = (const float*)d_in[5];
    const float* ln1g  = (const float*)d_in[6];
    const float* ln1b  = (const float*)d_in[7];
    const float* wf1   = (const float*)d_in[8];
    const float* bf1   = (const float*)d_in[9];
    const float* wf2   = (const float*)d_in[10];
    const float* bf2   = (const float*)d_in[11];
    const float* wf3   = (const float*)d_in[12];
    const float* bf3   = (const float*)d_in[13];
    const float* wf4   = (const float*)d_in[14];
    const float* bf4   = (const float*)d_in[15];
    const float* ln2g  = (const float*)d_in[16];
    const float* ln2b  = (const float*)d_in[17];
    float* out = (float*)d_out;

    cudaFuncSetAttribute(k_logits_tc, cudaFuncAttributeMaxDynamicSharedMemorySize, K1TC_SMEM);
    cudaFuncSetAttribute(k_cqa,       cudaFuncAttributeMaxDynamicSharedMemorySize, K5_SMEM);

    k_tsplit<<<dim3(16,16), 256>>>(w1, 0);
    k_tsplit<<<dim3(2,16),  256>>>(w2, 1);
    k_tsplit<<<dim3(16,16), 256>>>(wf1, 2);
    k_tsplit<<<dim3(16,16), 256>>>(wf2, 3);
    k_tsplit<<<dim3(16,16), 256>>>(wf3, 4);
    k_tsplit<<<dim3(16,16), 256>>>(wf4, 5);
    k_logits_tc<<<BB*TT/128, 512, K1TC_SMEM>>>(input, b1, b2);
    k_stats<<<BB, 256>>>();
    k_feat_tc<<<dim3(4, BB, 4), 256>>>(input);
    k_red_ln<<<ROWS, 256>>>(ln1g, ln1b);
    k_cqa<<<BB, 256, K5_SMEM>>>(query);
    k_headgemm_tc<<<dim3(4, 32), 256>>>(bf1, bf2, bf3, bf4);
    k_ln2<<<ROWS/8, 256>>>(ln2g, ln2b, out);
}

// round 11
// speedup vs baseline: 2.1899x; 1.0625x over previous
#include <cuda_runtime.h>
#include <cuda_bf16.h>
#include <cstdint>
#include <cmath>

#define BB 32
#define TT 4096
#define LL 32
#define DD 512
#define NN 64
#define ROWS (BB*NN)          // 2048

// ---------------- scratch (device globals; no allocs allowed) ----------------
__device__ float g_logits[BB*TT*NN];        // [B*T][64]   32 MB
__device__ float g_m[ROWS];
__device__ float g_rs[ROWS];
__device__ float g_pmax[1024*64];           // per-CTA partial max
__device__ float g_psum[1024*64];           // per-CTA partial sumexp
__device__ float g_part[4*ROWS*DD];         // t-split partial feat sums, 16 MB
__device__ float g_U[ROWS*2048];
__device__ float g_cat[ROWS*DD];
__device__ __nv_bfloat16 g_w1t_hi[DD*DD];   // [n=512][k=512]
__device__ __nv_bfloat16 g_w1t_lo[DD*DD];
__device__ __nv_bfloat16 g_w2t_hi[NN*DD];   // [n=64][k=512]
__device__ __nv_bfloat16 g_w2t_lo[NN*DD];
__device__ __nv_bfloat16 g_wft_hi[DD*2048]; // [n=512][k=2048]
__device__ __nv_bfloat16 g_wft_lo[DD*2048];

__device__ __forceinline__ float gelu_exact(float x) {
    return 0.5f * x * (1.0f + erff(x * 0.70710678118654752f));
}

// ===================== mma.sync / ldmatrix helpers =====================
__device__ __forceinline__ uint32_t smem_u32(const void* p) {
    uint32_t a;
    asm("{ .reg .u64 t; cvta.to.shared.u64 t, %1; cvt.u32.u64 %0, t; }" : "=r"(a) : "l"(p));
    return a;
}
__device__ __forceinline__ void ldsm_x4(uint32_t r[4], uint32_t addr) {
    asm volatile("ldmatrix.sync.aligned.m8n8.x4.shared.b16 {%0,%1,%2,%3}, [%4];"
        : "=r"(r[0]), "=r"(r[1]), "=r"(r[2]), "=r"(r[3]) : "r"(addr));
}
__device__ __forceinline__ void ldsm_x2(uint32_t r[2], uint32_t addr) {
    asm volatile("ldmatrix.sync.aligned.m8n8.x2.shared.b16 {%0,%1}, [%2];"
        : "=r"(r[0]), "=r"(r[1]) : "r"(addr));
}
__device__ __forceinline__ void ldsm_x2t(uint32_t r[2], uint32_t addr) {
    asm volatile("ldmatrix.sync.aligned.m8n8.x2.trans.shared.b16 {%0,%1}, [%2];"
        : "=r"(r[0]), "=r"(r[1]) : "r"(addr));
}
__device__ __forceinline__ void mma_bf16(float* d, const uint32_t* a, const uint32_t* b) {
    asm volatile("mma.sync.aligned.m16n8k16.row.col.f32.bf16.bf16.f32 "
        "{%0,%1,%2,%3}, {%4,%5,%6,%7}, {%8,%9}, {%0,%1,%2,%3};"
        : "+f"(d[0]), "+f"(d[1]), "+f"(d[2]), "+f"(d[3])
        : "r"(a[0]), "r"(a[1]), "r"(a[2]), "r"(a[3]), "r"(b[0]), "r"(b[1]));
}
__device__ __forceinline__ uint32_t pack_bf16(__nv_bfloat16 a, __nv_bfloat16 b) {
    return ((uint32_t)__bfloat16_as_ushort(b) << 16) | (uint32_t)__bfloat16_as_ushort(a);
}
__device__ __forceinline__ void split_bf16(float x, __nv_bfloat16& h, __nv_bfloat16& l) {
    h = __float2bfloat16(x);
    l = __float2bfloat16(x - __bfloat162float(h));
}

// =====================================================================
// K0: coalesced transpose + split.
// =====================================================================
__device__ __forceinline__ void tsplit_body(const float* __restrict__ src,
                                            int ncols, int dstride, int doff,
                                            __nv_bfloat16* dh, __nv_bfloat16* dl,
                                            int n0, int k0, int tx, int ty,
                                            float tile[32][33])
{
    #pragma unroll
    for (int i = 0; i < 4; i++) {
        int r = ty + i*8;
        tile[r][tx] = src[(size_t)(k0 + r)*ncols + n0 + tx];
    }
    __syncthreads();
    #pragma unroll
    for (int i = 0; i < 4; i++) {
        int r = ty + i*8;
        float x = tile[tx][r];
        __nv_bfloat16 h, l; split_bf16(x, h, l);
        size_t o = (size_t)(n0 + r)*dstride + doff + k0 + tx;
        dh[o] = h; dl[o] = l;
    }
}

__global__ void __launch_bounds__(256) k_tsplit(const float* __restrict__ src, int sel)
{
    __shared__ float tile[32][33];
    int ncols, dstride, doff;
    __nv_bfloat16 *dh, *dl;
    if (sel == 0)      { ncols = 512; dstride = 512;  doff = 0; dh = g_w1t_hi; dl = g_w1t_lo; }
    else               { ncols = 512; dstride = 2048; doff = (sel-2)*512; dh = g_wft_hi; dl = g_wft_lo; }
    const int n0 = blockIdx.x * 32, k0 = blockIdx.y * 32;
    const int tx = threadIdx.x & 31, ty = threadIdx.x >> 5;
    tsplit_body(src, ncols, dstride, doff, dh, dl, n0, k0, tx, ty, tile);
}

// combined: blocks x<2 -> w2 (sel1), else wf4 (sel5). Keeps launch count at 5
// so the 6th launch (profiled by ncu -s 5 -c 1) is k_logits_tc.
__global__ void __launch_bounds__(256) k_tsplit2(const float* __restrict__ w2,
                                                 const float* __restrict__ wf4)
{
    __shared__ float tile[32][33];
    const int tx = threadIdx.x & 31, ty = threadIdx.x >> 5;
    const int k0 = blockIdx.y * 32;
    if (blockIdx.x < 2) {
        tsplit_body(w2, 64, 512, 0, g_w2t_hi, g_w2t_lo, blockIdx.x*32, k0, tx, ty, tile);
    } else {
        tsplit_body(wf4, 512, 2048, 3*512, g_wft_hi, g_wft_lo, (blockIdx.x-2)*32, k0, tx, ty, tile);
    }
}

// =====================================================================
// K1: split-bf16 mma.sync  logits = GELU(X@w1+b1)@w2 + b2
// Double-buffered GEMM1 (1 sync/chunk), x4 B-loads, fused partial softmax stats.
// grid 1024, 512 thr, dyn smem 194816 B
// =====================================================================
#define SM1_XH0   0
#define SM1_XH1   10240
#define SM1_XL0   20480
#define SM1_XL1   30720
#define SM1_W1H0  40960
#define SM1_W1H1  61440
#define SM1_W1L0  81920
#define SM1_W1L1  102400
#define SM1_HHI   122880     // [128][272B] = 34816 ; reused as fp32 stage [128][64]
#define SM1_HLO   157696
#define SM1_W2H   0          // reuses X region during GEMM2
#define SM1_W2L   5120
#define SM1_B1    192512
#define SM1_B2    194560
#define K1TC_SMEM 194816

__global__ void __launch_bounds__(512, 1) k_logits_tc(
    const float* __restrict__ input,
    const float* __restrict__ b1, const float* __restrict__ b2)
{
    extern __shared__ char smem[];
    const uint32_t sb = smem_u32(smem);
    const int tid = threadIdx.x;
    const int wid = tid >> 5, lane = tid & 31;
    const int wm = wid & 3, wn = wid >> 2;       // 4(M) x 4(N)
    const size_t t0 = (size_t)blockIdx.x * 128;

    float* b1s = (float*)(smem + SM1_B1);
    float* b2s = (float*)(smem + SM1_B2);
    b1s[tid & 511] = b1[tid & 511];
    if (tid < 64) b2s[tid] = b2[tid];

    const uint32_t aoffX = (uint32_t)((lane & 15) * 80  + (lane >> 4) * 16);
    const uint32_t aoffH = (uint32_t)((lane & 15) * 272 + (lane >> 4) * 16);
    // x4 B-operand lane map: lanes 0-15 -> rows 0-7 (k halves), lanes 16-31 -> rows 8-15
    const uint32_t boffW4 = (uint32_t)(((lane & 7) + (lane >> 4) * 8) * 80 + ((lane >> 3) & 1) * 16);
    const int qrow = lane >> 2, qcol = (lane & 3) * 2;

    const int xrow = tid >> 2, xseg = tid & 3;
    const int w1n  = tid >> 1, w1p  = tid & 1;
    const int w2n  = tid >> 3, w2s  = tid & 7;

    float acc2[2][2][4];
    #pragma unroll
    for (int i = 0; i < 2; i++)
        #pragma unroll
        for (int j = 0; j < 2; j++)
            #pragma unroll
            for (int k = 0; k < 4; k++) acc2[i][j][k] = 0.0f;

    for (int nc = 0; nc < 2; nc++) {
        float acc[2][8][4];
        #pragma unroll
        for (int i = 0; i < 2; i++)
            #pragma unroll
            for (int j = 0; j < 8; j++)
                #pragma unroll
                for (int k = 0; k < 4; k++) acc[i][j][k] = 0.0f;

        float4 xr0, xr1;
        uint4 w1r[4];
        {
            const float* s = input + (t0 + xrow)*DD + xseg*8;
            xr0 = *(const float4*)s; xr1 = *(const float4*)(s + 4);
            const uint4* sh = (const uint4*)(g_w1t_hi + (size_t)(nc*256 + w1n)*512 + w1p*16);
            const uint4* sl = (const uint4*)(g_w1t_lo + (size_t)(nc*256 + w1n)*512 + w1p*16);
            w1r[0] = sh[0]; w1r[1] = sh[1]; w1r[2] = sl[0]; w1r[3] = sl[1];
        }

        for (int kc = 0; kc < 16; kc++) {
            const uint32_t bufX  = (kc & 1) ? SM1_XH1  : SM1_XH0;
            const uint32_t bufXL = (kc & 1) ? SM1_XL1  : SM1_XL0;
            const uint32_t bufW  = (kc & 1) ? SM1_W1H1 : SM1_W1H0;
            const uint32_t bufWL = (kc & 1) ? SM1_W1L1 : SM1_W1L0;
            {
                __nv_bfloat16 h[8], l[8];
                split_bf16(xr0.x, h[0], l[0]); split_bf16(xr0.y, h[1], l[1]);
                split_bf16(xr0.z, h[2], l[2]); split_bf16(xr0.w, h[3], l[3]);
                split_bf16(xr1.x, h[4], l[4]); split_bf16(xr1.y, h[5], l[5]);
                split_bf16(xr1.z, h[6], l[6]); split_bf16(xr1.w, h[7], l[7]);
                uint4 hp = { pack_bf16(h[0],h[1]), pack_bf16(h[2],h[3]),
                             pack_bf16(h[4],h[5]), pack_bf16(h[6],h[7]) };
                uint4 lp = { pack_bf16(l[0],l[1]), pack_bf16(l[2],l[3]),
                             pack_bf16(l[4],l[5]), pack_bf16(l[6],l[7]) };
                *(uint4*)(smem + bufX  + xrow*80 + xseg*16) = hp;
                *(uint4*)(smem + bufXL + xrow*80 + xseg*16) = lp;
                char* dh = smem + bufW  + w1n*80 + w1p*32;
                char* dl = smem + bufWL + w1n*80 + w1p*32;
                *(uint4*)dh = w1r[0]; *(uint4*)(dh + 16) = w1r[1];
                *(uint4*)dl = w1r[2]; *(uint4*)(dl + 16) = w1r[3];
            }
            if (kc < 15) {
                const float* s = input + (t0 + xrow)*DD + (kc+1)*32 + xseg*8;
                xr0 = *(const float4*)s; xr1 = *(const float4*)(s + 4);
                const uint4* sh = (const uint4*)(g_w1t_hi + (size_t)(nc*256 + w1n)*512 + (kc+1)*32 + w1p*16);
                const uint4* sl = (const uint4*)(g_w1t_lo + (size_t)(nc*256 + w1n)*512 + (kc+1)*32 + w1p*16);
                w1r[0] = sh[0]; w1r[1] = sh[1]; w1r[2] = sl[0]; w1r[3] = sl[1];
            }
            __syncthreads();
            const uint32_t xsrc[3] = {bufX, bufX, bufXL};
            const uint32_t wsrc[3] = {bufW, bufWL, bufW};
            #pragma unroll
            for (int p = 0; p < 3; p++) {
                uint32_t xb = sb + xsrc[p] + aoffX + (uint32_t)(wm*32*80);
                uint32_t wb = sb + wsrc[p] + boffW4 + (uint32_t)(wn*64*80);
                #pragma unroll
                for (int ks = 0; ks < 2; ks++) {
                    uint32_t a0[4], a1[4];
                    ldsm_x4(a0, xb + ks*32);
                    ldsm_x4(a1, xb + 16*80 + ks*32);
                    #pragma unroll
                    for (int nt = 0; nt < 8; nt += 2) {
                        uint32_t bq[4];
                        ldsm_x4(bq, wb + nt*8*80 + ks*32);
                        mma_bf16(acc[0][nt],   a0, bq);
                        mma_bf16(acc[1][nt],   a1, bq);
                        mma_bf16(acc[0][nt+1], a0, bq + 2);
                        mma_bf16(acc[1][nt+1], a1, bq + 2);
                    }
                }
            }
        }

        for (int h = 0; h < 2; h++) {
            if (h) __syncthreads();
            if ((wn >> 1) == h) {
                #pragma unroll
                for (int mt = 0; mt < 2; mt++)
                    #pragma unroll
                    for (int nt = 0; nt < 8; nt++)
                        #pragma unroll
                        for (int hh = 0; hh < 2; hh++) {
                            int row = wm*32 + mt*16 + hh*8 + qrow;
                            int col = wn*64 + nt*8 + qcol;
                            float x0 = acc[mt][nt][hh*2+0] + b1s[nc*256 + col];
                            float x1 = acc[mt][nt][hh*2+1] + b1s[nc*256 + col + 1];
                            float g0 = gelu_exact(x0), g1 = gelu_exact(x1);
                            __nv_bfloat16 hh0, ll0, hh1, ll1;
                            split_bf16(g0, hh0, ll0); split_bf16(g1, hh1, ll1);
                            int c = col & 127;
                            *(uint32_t*)(smem + SM1_HHI + row*272 + c*2) = pack_bf16(hh0, hh1);
                            *(uint32_t*)(smem + SM1_HLO + row*272 + c*2) = pack_bf16(ll0, ll1);
                        }
            }
            __syncthreads();

            for (int kc2 = 0; kc2 < 4; kc2++) {
                if (kc2 > 0) __syncthreads();
                {
                    const int koff = w2s * 4;
                    *(uint2*)(smem + SM1_W2H + w2n*80 + w2s*8) =
                        *(const uint2*)(g_w2t_hi + (size_t)w2n*512 + nc*256 + h*128 + kc2*32 + koff);
                    *(uint2*)(smem + SM1_W2L + w2n*80 + w2s*8) =
                        *(const uint2*)(g_w2t_lo + (size_t)w2n*512 + nc*256 + h*128 + kc2*32 + koff);
                }
                __syncthreads();
                const uint32_t hsrc[3]  = {SM1_HHI, SM1_HHI, SM1_HLO};
                const uint32_t w2src[3] = {SM1_W2H, SM1_W2L, SM1_W2H};
                #pragma unroll
                for (int p = 0; p < 3; p++) {
                    uint32_t hb  = sb + hsrc[p]  + aoffH + (uint32_t)(wm*32*272) + (uint32_t)(kc2*64);
                    uint32_t w2b = sb + w2src[p] + boffW4 + (uint32_t)(wn*16*80);
                    #pragma unroll
                    for (int ks = 0; ks < 2; ks++) {
                        uint32_t a0[4], a1[4];
                        ldsm_x4(a0, hb + ks*32);
                        ldsm_x4(a1, hb + 16*272 + ks*32);
                        uint32_t bq[4];
                        ldsm_x4(bq, w2b + ks*32);
                        mma_bf16(acc2[0][0], a0, bq);
                        mma_bf16(acc2[1][0], a1, bq);
                        mma_bf16(acc2[0][1], a0, bq + 2);
                        mma_bf16(acc2[1][1], a1, bq + 2);
                    }
                }
            }
            __syncthreads();
        }
    }

    // ---------------- store logits (+b2), stage for partial stats ----------------
    float* stg = (float*)(smem + SM1_HHI);   // [128][64] fp32; HHI free after final sync above
    #pragma unroll
    for (int mt = 0; mt < 2; mt++)
        #pragma unroll
        for (int nt = 0; nt < 2; nt++)
            #pragma unroll
            for (int h = 0; h < 2; h++) {
                int row = wm*32 + mt*16 + h*8 + qrow;
                int col = wn*16 + nt*8 + qcol;
                float2 v;
                v.x = acc2[mt][nt][h*2+0] + b2s[col];
                v.y = acc2[mt][nt][h*2+1] + b2s[col+1];
                *(float2*)(g_logits + (t0 + row)*NN + col) = v;
                *(float2*)(stg + row*64 + col) = v;
            }
    __syncthreads();
    if (tid < 64) {
        float M = -1e30f;
        #pragma unroll 8
        for (int r = 0; r < 128; r++) M = fmaxf(M, stg[r*64 + tid]);
        float S = 0.0f;
        #pragma unroll 8
        for (int r = 0; r < 128; r++) S += __expf(stg[r*64 + tid] - M);
        g_pmax[(size_t)blockIdx.x*64 + tid] = M;
        g_psum[(size_t)blockIdx.x*64 + tid] = S;
    }
}

// =====================================================================
// K2: combine per-CTA partial stats.  grid 32, 64 thr, reads 512 KB.
// =====================================================================
__global__ void __launch_bounds__(64) k_stats()
{
    const int b = blockIdx.x, n = threadIdx.x;
    float M = -1e30f;
    #pragma unroll
    for (int p = 0; p < 32; p++)
        M = fmaxf(M, g_pmax[(size_t)(b*32 + p)*64 + n]);
    float S = 0.0f;
    #pragma unroll
    for (int p = 0; p < 32; p++)
        S += g_psum[(size_t)(b*32 + p)*64 + n] * __expf(g_pmax[(size_t)(b*32 + p)*64 + n] - M);
    g_m[b*NN + n] = M;
    g_rs[b*NN + n] = 1.0f / S;
}

// =====================================================================
// K3: feat partials via split-bf16 mma.sync.  (unchanged from R10)
// =====================================================================
#define FT_PP 80
#define FT_XP 272
__global__ void __launch_bounds__(256, 2) k_feat_tc(const float* __restrict__ input)
{
    __shared__ __align__(16) char PH[64*FT_PP], PL[64*FT_PP];
    __shared__ __align__(16) char XH[32*FT_XP], XL[32*FT_XP];
    __shared__ float ms[64];

    const int b = blockIdx.y;
    const int d0 = blockIdx.x * 128;
    const int ts = blockIdx.z;
    const int tid = threadIdx.x;
    const int wid = tid >> 5, lane = tid & 31;
    const int wm = wid & 1, wn = wid >> 1;
    if (tid < 64) ms[tid] = g_m[b*NN + tid];

    const uint32_t phB = smem_u32(PH), plB = smem_u32(PL);
    const uint32_t xhB = smem_u32(XH), xlB = smem_u32(XL);
    const uint32_t aoff = (uint32_t)((lane & 15) * FT_PP + (lane >> 4) * 16);
    const uint32_t boffT = (uint32_t)((lane & 15) * FT_XP);
    const int qrow = lane >> 2, qcol = (lane & 3) * 2;

    const int pt = tid >> 3, pn8 = (tid & 7) * 8;
    const int xt = tid >> 3, xds = (tid & 7) * 16;

    float acc[2][4][4];
    #pragma unroll
    for (int i = 0; i < 2; i++)
        #pragma unroll
        for (int j = 0; j < 4; j++)
            #pragma unroll
            for (int k = 0; k < 4; k++) acc[i][j][k] = 0.0f;

    const float* L = g_logits + (size_t)b*TT*NN;
    const float* X = input + (size_t)b*TT*DD;

    for (int kt = 0; kt < 32; kt++) {
        const int t0 = (ts*32 + kt) * 32;
        __syncthreads();
        {
            float4 v0 = *(const float4*)(L + (size_t)(t0+pt)*NN + pn8);
            float4 v1 = *(const float4*)(L + (size_t)(t0+pt)*NN + pn8 + 4);
            float e[8];
            e[0]=__expf(v0.x - ms[pn8+0]); e[1]=__expf(v0.y - ms[pn8+1]);
            e[2]=__expf(v0.z - ms[pn8+2]); e[3]=__expf(v0.w - ms[pn8+3]);
            e[4]=__expf(v1.x - ms[pn8+4]); e[5]=__expf(v1.y - ms[pn8+5]);
            e[6]=__expf(v1.z - ms[pn8+6]); e[7]=__expf(v1.w - ms[pn8+7]);
            #pragma unroll
            for (int j = 0; j < 8; j++) {
                __nv_bfloat16 h, l; split_bf16(e[j], h, l);
                *(uint16_t*)(PH + (pn8+j)*FT_PP + pt*2) = __bfloat16_as_ushort(h);
                *(uint16_t*)(PL + (pn8+j)*FT_PP + pt*2) = __bfloat16_as_ushort(l);
            }
        }
        {
            const float* s = X + (size_t)(t0+xt)*DD + d0 + xds;
            float4 v0 = *(const float4*)s,      v1 = *(const float4*)(s+4);
            float4 v2 = *(const float4*)(s+8),  v3 = *(const float4*)(s+12);
            __nv_bfloat16 h[16], l[16];
            split_bf16(v0.x,h[0],l[0]);  split_bf16(v0.y,h[1],l[1]);
            split_bf16(v0.z,h[2],l[2]);  split_bf16(v0.w,h[3],l[3]);
            split_bf16(v1.x,h[4],l[4]);  split_bf16(v1.y,h[5],l[5]);
            split_bf16(v1.z,h[6],l[6]);  split_bf16(v1.w,h[7],l[7]);
            split_bf16(v2.x,h[8],l[8]);  split_bf16(v2.y,h[9],l[9]);
            split_bf16(v2.z,h[10],l[10]); split_bf16(v2.w,h[11],l[11]);
            split_bf16(v3.x,h[12],l[12]); split_bf16(v3.y,h[13],l[13]);
            split_bf16(v3.z,h[14],l[14]); split_bf16(v3.w,h[15],l[15]);
            uint4 hp0 = { pack_bf16(h[0],h[1]), pack_bf16(h[2],h[3]),
                          pack_bf16(h[4],h[5]), pack_bf16(h[6],h[7]) };
            uint4 hp1 = { pack_bf16(h[8],h[9]), pack_bf16(h[10],h[11]),
                          pack_bf16(h[12],h[13]), pack_bf16(h[14],h[15]) };
            uint4 lp0 = { pack_bf16(l[0],l[1]), pack_bf16(l[2],l[3]),
                          pack_bf16(l[4],l[5]), pack_bf16(l[6],l[7]) };
            uint4 lp1 = { pack_bf16(l[8],l[9]), pack_bf16(l[10],l[11]),
                          pack_bf16(l[12],l[13]), pack_bf16(l[14],l[15]) };
            char* dh = XH + xt*FT_XP + xds*2;
            char* dl = XL + xt*FT_XP + xds*2;
            *(uint4*)dh = hp0; *(uint4*)(dh+16) = hp1;
            *(uint4*)dl = lp0; *(uint4*)(dl+16) = lp1;
        }
        __syncthreads();
        const uint32_t asrc[3] = {phB, phB, plB};
        const uint32_t bsrc[3] = {xhB, xlB, xhB};
        #pragma unroll
        for (int p = 0; p < 3; p++) {
            uint32_t ab = asrc[p] + aoff + (uint32_t)(wm*32*FT_PP);
            uint32_t bb = bsrc[p] + boffT + (uint32_t)((wn*32)*2);
            #pragma unroll
            for (int ks = 0; ks < 2; ks++) {
                uint32_t a0[4], a1[4];
                ldsm_x4(a0, ab + ks*32);
                ldsm_x4(a1, ab + 16*FT_PP + ks*32);
                #pragma unroll
                for (int nt = 0; nt < 4; nt++) {
                    uint32_t bf[2];
                    ldsm_x2t(bf, bb + (uint32_t)(ks*16*FT_XP) + (uint32_t)(nt*16));
                    mma_bf16(acc[0][nt], a0, bf);
                    mma_bf16(acc[1][nt], a1, bf);
                }
            }
        }
    }

    float* base = g_part + (size_t)ts*ROWS*DD + (size_t)(b*NN)*DD + d0;
    #pragma unroll
    for (int mt = 0; mt < 2; mt++)
        #pragma unroll
        for (int nt = 0; nt < 4; nt++)
            #pragma unroll
            for (int h = 0; h < 2; h++) {
                int n = wm*32 + mt*16 + h*8 + qrow;
                int d = wn*32 + nt*8 + qcol;
                float2 v = { acc[mt][nt][h*2+0], acc[mt][nt][h*2+1] };
                *(float2*)(base + (size_t)n*DD + d) = v;
            }
}

// =====================================================================
// K3b: reduce 4 partials, scale by 1/S, fused LayerNorm1 -> g_U seg 0.
// =====================================================================
__global__ void __launch_bounds__(256) k_red_ln(const float* __restrict__ gamma,
                                               const float* __restrict__ beta)
{
    const int row = blockIdx.x;
    const int tid = threadIdx.x, lane = tid & 31, wid = tid >> 5;
    const float r = g_rs[row];
    const size_t o = (size_t)row*DD;

    float v0 = 0.0f, v1 = 0.0f;
    #pragma unroll
    for (int ts = 0; ts < 4; ts++) {
        v0 += g_part[(size_t)ts*ROWS*DD + o + tid];
        v1 += g_part[(size_t)ts*ROWS*DD + o + tid + 256];
    }
    v0 *= r; v1 *= r;

    float s = v0 + v1, sq = v0*v0 + v1*v1;
    #pragma unroll
    for (int off = 16; off > 0; off >>= 1) {
        s  += __shfl_xor_sync(0xffffffffu, s, off);
        sq += __shfl_xor_sync(0xffffffffu, sq, off);
    }
    __shared__ float ss[8], sqs[8], bc[2];
    if (lane == 0) { ss[wid] = s; sqs[wid] = sq; }
    __syncthreads();
    if (wid == 0) {
        float s2 = (lane < 8) ? ss[lane] : 0.0f;
        float q2 = (lane < 8) ? sqs[lane] : 0.0f;
        #pragma unroll
        for (int off = 4; off > 0; off >>= 1) {
            s2 += __shfl_xor_sync(0xffffffffu, s2, off);
            q2 += __shfl_xor_sync(0xffffffffu, q2, off);
        }
        if (lane == 0) {
            float mean = s2 * (1.0f/512.0f);
            float var  = q2 * (1.0f/512.0f) - mean*mean;
            bc[0] = mean;
            bc[1] = rsqrtf(var + 1e-5f);
        }
    }
    __syncthreads();
    float mean = bc[0], inv = bc[1];
    float* dst = g_U + (size_t)row*2048;
    dst[tid]       = (v0 - mean)*inv*gamma[tid]       + beta[tid];
    dst[tid + 256] = (v1 - mean)*inv*gamma[tid + 256] + beta[tid + 256];
}

// =====================================================================
// LayerNorm helper: one warp per 512-wide row
// =====================================================================
__device__ __forceinline__ void ln_row(const float* __restrict__ src,
                                       float* __restrict__ dst,
                                       const float* __restrict__ gamma,
                                       const float* __restrict__ beta,
                                       int lane)
{
    float4 v[4];
    float s = 0.0f, sq = 0.0f;
    #pragma unroll
    for (int i = 0; i < 4; i++) {
        v[i] = *(const float4*)(src + i*128 + lane*4);
        s  += v[i].x + v[i].y + v[i].z + v[i].w;
        sq += v[i].x*v[i].x + v[i].y*v[i].y + v[i].z*v[i].z + v[i].w*v[i].w;
    }
    #pragma unroll
    for (int o = 16; o > 0; o >>= 1) {
        s  += __shfl_xor_sync(0xffffffffu, s, o);
        sq += __shfl_xor_sync(0xffffffffu, sq, o);
    }
    float mean = s * (1.0f/512.0f);
    float var  = sq * (1.0f/512.0f) - mean*mean;
    float inv  = rsqrtf(var + 1e-5f);
    #pragma unroll
    for (int i = 0; i < 4; i++) {
        int c = i*128 + lane*4;
        float4 g4 = *(const float4*)(gamma + c);
        float4 b4 = *(const float4*)(beta + c);
        float4 o;
        o.x = (v[i].x - mean)*inv*g4.x + b4.x;
        o.y = (v[i].y - mean)*inv*g4.y + b4.y;
        o.z = (v[i].z - mean)*inv*g4.z + b4.z;
        o.w = (v[i].w - mean)*inv*g4.w + b4.w;
        *(float4*)(dst + c) = o;
    }
}

// =====================================================================
// K5: per-batch CQA core. grid 32, 256 thr, dyn smem 214016 B (unchanged)
// =====================================================================
#define QS_STRIDE 516
#define K5_SMEM ((LL*QS_STRIDE + NN*DD + 2*NN*33) * 4)
__global__ void __launch_bounds__(256) k_cqa(const float* __restrict__ query)
{
    extern __shared__ float sm[];
    float* qs = sm;
    float* fs = qs + LL*QS_STRIDE;
    float* s0 = fs + NN*DD;
    float* sr = s0 + NN*33;

    const int b = blockIdx.x, tid = threadIdx.x;

    for (int i = tid; i < LL*128; i += 256) {
        int l = i >> 7, c4 = i & 127;
        *(float4*)(qs + l*QS_STRIDE + c4*4) =
            *(const float4*)(query + (size_t)(b*LL + l)*DD + c4*4);
    }
    for (int i = tid; i < NN*128; i += 256) {
        int n = i >> 7, c4 = i & 127;
        *(float4*)(fs + n*DD + c4*4) =
            *(const float4*)(g_U + (size_t)(b*NN + n)*2048 + c4*4);
    }
    __syncthreads();

    {
        const int l = tid & 31, ng = tid >> 5;
        #pragma unroll
        for (int j = 0; j < 8; j++) {
            int n = ng + 8*j;
            float s = 0.0f;
            #pragma unroll 4
            for (int k = 0; k < DD; k++) s += fs[n*DD + k] * qs[l*QS_STRIDE + k];
            s0[n*33 + l] = s;
        }
    }
    __syncthreads();
    if (tid < 64) {
        int n = tid;
        float M = -1e30f;
        for (int l = 0; l < 32; l++) M = fmaxf(M, s0[n*33 + l]);
        float S = 0.0f;
        for (int l = 0; l < 32; l++) S += __expf(s0[n*33 + l] - M);
        float inv = 1.0f / S;
        for (int l = 0; l < 32; l++) sr[n*33 + l] = __expf(s0[n*33 + l] - M) * inv;
    }
    __syncthreads();
    if (tid < 32) {
        int l = tid;
        float M = -1e30f;
        for (int n = 0; n < 64; n++) M = fmaxf(M, s0[n*33 + l]);
        float S = 0.0f;
        for (int n = 0; n < 64; n++) S += __expf(s0[n*33 + l] - M);
        float inv = 1.0f / S;
        for (int n = 0; n < 64; n++) s0[n*33 + l] = __expf(s0[n*33 + l] - M) * inv;
    }
    __syncthreads();

    for (int i = tid; i < NN*128; i += 256) {
        int n = i >> 7, c4 = i & 127, d = c4*4;
        float4 a = {0,0,0,0};
        #pragma unroll
        for (int l = 0; l < 32; l++) {
            float w = sr[n*33 + l];
            float4 qv = *(const float4*)(qs + l*QS_STRIDE + d);
            a.x += w*qv.x; a.y += w*qv.y; a.z += w*qv.z; a.w += w*qv.w;
        }
        float4 f = *(const float4*)(fs + n*DD + d);
        float* dst = g_U + (size_t)(b*NN + n)*2048;
        *(float4*)(dst + 512 + d) = a;
        float4 e3 = {f.x*a.x, f.y*a.y, f.z*a.z, f.w*a.w};
        *(float4*)(dst + 1024 + d) = e3;
    }
    __syncthreads();

    for (int i = tid; i < LL*128; i += 256) {
        int l = i >> 7, c4 = i & 127, d = c4*4;
        float4 m = {0,0,0,0};
        #pragma unroll 8
        for (int n = 0; n < 64; n++) {
            float w = s0[n*33 + l];
            float4 fv = *(const float4*)(fs + n*DD + d);
            m.x += w*fv.x; m.y += w*fv.y; m.z += w*fv.z; m.w += w*fv.w;
        }
        *(float4*)(qs + l*QS_STRIDE + d) = m;
    }
    __syncthreads();

    for (int i = tid; i < NN*128; i += 256) {
        int n = i >> 7, c4 = i & 127, d = c4*4;
        float4 bm = {0,0,0,0};
        #pragma unroll
        for (int l = 0; l < 32; l++) {
            float w = sr[n*33 + l];
            float4 mv = *(const float4*)(qs + l*QS_STRIDE + d);
            bm.x += w*mv.x; bm.y += w*mv.y; bm.z += w*mv.z; bm.w += w*mv.w;
        }
        float4 f = *(const float4*)(fs + n*DD + d);
        float4 e4 = {f.x*bm.x, f.y*bm.y, f.z*bm.z, f.w*bm.w};
        *(float4*)(g_U + (size_t)(b*NN + n)*2048 + 1536 + d) = e4;
    }
}

// =====================================================================
// K6: split-bf16 mma.sync  cat = U @ Wf^T + bias  (unchanged)
// =====================================================================
__global__ void __launch_bounds__(256) k_headgemm_tc(
    const float* __restrict__ bf1, const float* __restrict__ bf2,
    const float* __restrict__ bf3, const float* __restrict__ bf4)
{
    __shared__ __align__(16) char Uh[64*80], Ul[64*80];
    __shared__ __align__(16) char Wh[128*80], Wl[128*80];
    __shared__ float bsum[128];

    const int tid = threadIdx.x;
    const int wid = tid >> 5, lane = tid & 31;
    const int wm = wid & 1, wn = wid >> 1;
    const int n0 = blockIdx.x * 128;
    const int m0 = blockIdx.y * 64;
    if (tid < 128) bsum[tid] = bf1[n0+tid] + bf2[n0+tid] + bf3[n0+tid] + bf4[n0+tid];

    const uint32_t uhB = smem_u32(Uh), ulB = smem_u32(Ul);
    const uint32_t whB = smem_u32(Wh), wlB = smem_u32(Wl);
    const uint32_t aoff = (uint32_t)((lane & 15) * 80 + (lane >> 4) * 16);
    const uint32_t boff = (uint32_t)((lane & 7)  * 80 + ((lane >> 3) & 1) * 16);
    const int qrow = lane >> 2, qcol = (lane & 3) * 2;

    float acc[2][4][4];
    #pragma unroll
    for (int i = 0; i < 2; i++)
        #pragma unroll
        for (int j = 0; j < 4; j++)
            #pragma unroll
            for (int k = 0; k < 4; k++) acc[i][j][k] = 0.0f;

    for (int kc = 0; kc < 64; kc++) {
        __syncthreads();
        {
            int r = tid >> 2, seg = tid & 3;
            const float* s = g_U + (size_t)(m0 + r)*2048 + kc*32 + seg*8;
            float4 v0 = *(const float4*)s;
            float4 v1 = *(const float4*)(s + 4);
            __nv_bfloat16 h[8], l[8];
            split_bf16(v0.x, h[0], l[0]); split_bf16(v0.y, h[1], l[1]);
            split_bf16(v0.z, h[2], l[2]); split_bf16(v0.w, h[3], l[3]);
            split_bf16(v1.x, h[4], l[4]); split_bf16(v1.y, h[5], l[5]);
            split_bf16(v1.z, h[6], l[6]); split_bf16(v1.w, h[7], l[7]);
            uint4 hp = { pack_bf16(h[0],h[1]), pack_bf16(h[2],h[3]),
                         pack_bf16(h[4],h[5]), pack_bf16(h[6],h[7]) };
            uint4 lp = { pack_bf16(l[0],l[1]), pack_bf16(l[2],l[3]),
                         pack_bf16(l[4],l[5]), pack_bf16(l[6],l[7]) };
            *(uint4*)(Uh + r*80 + seg*16) = hp;
            *(uint4*)(Ul + r*80 + seg*16) = lp;
        }
        {
            int nr = tid >> 1, part = tid & 1;
            const uint4* sh = (const uint4*)(g_wft_hi + (size_t)(n0 + nr)*2048 + kc*32 + part*16);
            const uint4* sl = (const uint4*)(g_wft_lo + (size_t)(n0 + nr)*2048 + kc*32 + part*16);
            uint4 h0 = sh[0], h1 = sh[1];
            uint4 l0 = sl[0], l1 = sl[1];
            char* dh = Wh + nr*80 + part*32;
            char* dl = Wl + nr*80 + part*32;
            *(uint4*)dh = h0; *(uint4*)(dh + 16) = h1;
            *(uint4*)dl = l0; *(uint4*)(dl + 16) = l1;
        }
        __syncthreads();
        const uint32_t usrc[3] = {uhB, uhB, ulB};
        const uint32_t wsrc[3] = {whB, wlB, whB};
        #pragma unroll
        for (int p = 0; p < 3; p++) {
            uint32_t ub = usrc[p] + aoff + (uint32_t)(wm*32*80);
            uint32_t wb = wsrc[p] + boff + (uint32_t)(wn*32*80);
            #pragma unroll
            for (int ks = 0; ks < 2; ks++) {
                uint32_t a0[4], a1[4];
                ldsm_x4(a0, ub + ks*32);
                ldsm_x4(a1, ub + 16*80 + ks*32);
                #pragma unroll
                for (int nt = 0; nt < 4; nt++) {
                    uint32_t bf[2];
                    ldsm_x2(bf, wb + nt*8*80 + ks*32);
                    mma_bf16(acc[0][nt], a0, bf);
                    mma_bf16(acc[1][nt], a1, bf);
                }
            }
        }
    }

    #pragma unroll
    for (int mt = 0; mt < 2; mt++)
        #pragma unroll
        for (int nt = 0; nt < 4; nt++)
            #pragma unroll
            for (int h = 0; h < 2; h++) {
                int row = m0 + wm*32 + mt*16 + h*8 + qrow;
                int col = wn*32 + nt*8 + qcol;
                float2 v;
                v.x = acc[mt][nt][h*2+0] + bsum[col];
                v.y = acc[mt][nt][h*2+1] + bsum[col+1];
                *(float2*)(g_cat + (size_t)row*DD + n0 + col) = v;
            }
}

// K7: LN2(cat) -> d_out.  grid 256, 256 thr
__global__ void __launch_bounds__(256) k_ln2(const float* __restrict__ g,
                                             const float* __restrict__ be,
                                             float* __restrict__ out)
{
    int warp = threadIdx.x >> 5, lane = threadIdx.x & 31;
    int row = blockIdx.x * 8 + warp;
    ln_row(g_cat + (size_t)row*DD, out + (size_t)row*DD, g, be, lane);
}

// =====================================================================
extern "C" void kernel_launch(void* const* d_in, const int* in_sizes, int n_in,
                              void* d_out, int out_size)
{
    const float* input = (const float*)d_in[0];
    const float* query = (const float*)d_in[1];
    const float* w1    = (const float*)d_in[2];
    const float* b1    = (const float*)d_in[3];
    const float* w2    = (const float*)d_in[4];
    const float* b2    = (const float*)d_in[5];
    const float* ln1g  = (const float*)d_in[6];
    const float* ln1b  = (const float*)d_in[7];
    const float* wf1   = (const float*)d_in[8];
    const float* bf1   = (const float*)d_in[9];
    const float* wf2   = (const float*)d_in[10];
    const float* bf2   = (const float*)d_in[11];
    const float* wf3   = (const float*)d_in[12];
    const float* bf3   = (const float*)d_in[13];
    const float* wf4   = (const float*)d_in[14];
    const float* bf4   = (const float*)d_in[15];
    const float* ln2g  = (const float*)d_in[16];
    const float* ln2b  = (const float*)d_in[17];
    float* out = (float*)d_out;

    cudaFuncSetAttribute(k_logits_tc, cudaFuncAttributeMaxDynamicSharedMemorySize, K1TC_SMEM);
    cudaFuncSetAttribute(k_cqa,       cudaFuncAttributeMaxDynamicSharedMemorySize, K5_SMEM);

    // 5 prep launches; launch #6 (= k_logits_tc) is what ncu -s 5 -c 1 profiles.
    k_tsplit<<<dim3(16,16), 256>>>(w1, 0);
    k_tsplit<<<dim3(16,16), 256>>>(wf1, 2);
    k_tsplit<<<dim3(16,16), 256>>>(wf2, 3);
    k_tsplit<<<dim3(16,16), 256>>>(wf3, 4);
    k_tsplit2<<<dim3(18,16), 256>>>(w2, wf4);
    k_logits_tc<<<BB*TT/128, 512, K1TC_SMEM>>>(input, b1, b2);
    k_stats<<<BB, 64>>>();
    k_feat_tc<<<dim3(4, BB, 4), 256>>>(input);
    k_red_ln<<<ROWS, 256>>>(ln1g, ln1b);
    k_cqa<<<BB, 256, K5_SMEM>>>(query);
    k_headgemm_tc<<<dim3(4, 32), 256>>>(bf1, bf2, bf3, bf4);
    k_ln2<<<ROWS/8, 256>>>(ln2g, ln2b, out);
}